// round 15
// baseline (speedup 1.0000x reference)
#include <cuda_runtime.h>
#include <cuda_bf16.h>
#include <math.h>
#include <stdint.h>

// ---------------------------------------------------------------------------
// Problem constants
// ---------------------------------------------------------------------------
namespace {
constexpr int Bn = 256, Sn = 128, En = 300, Pn = 200, Cn = 3;
constexpr long BS = (long)Bn * Sn;  // 32768
constexpr int EP = 304;             // 300 padded to 16B multiple

// ---- f32 scratch (masks + pool)
constexpr long OFF_MASK1 = 0;
constexpr long OFF_MASK2 = OFF_MASK1 + BS;
constexpr long OFF_POOL  = OFF_MASK2 + BS;
constexpr long F32_TOTAL = OFF_POOL + (long)Bn * 4 * Pn;

// ---- bf16 activation arena: every tensor is two planes (hi, lo = +PLANE)
constexpr long ACT_CAT  = 0;                        // [2][BS][600]
constexpr long CAT_PL   = 2 * BS * 600;
constexpr long ACT_F    = ACT_CAT + 2 * CAT_PL;     // [2*BS][304]
constexpr long F_PL     = 2 * BS * EP;
constexpr long ACT_ATT  = ACT_F + 2 * F_PL;         // [2*B][S][S] (softmaxed)
constexpr long ATT_PL   = 2 * BS * Sn;
constexpr long ACT_CATP = ACT_ATT + 2 * ATT_PL;     // [2][BS][400]
constexpr long CATP_PL  = 2 * BS * 2 * Pn;
constexpr long ACT_FA   = ACT_CATP + 2 * CATP_PL;   // [2][BS][200]
constexpr long FA_PL    = 2 * BS * Pn;
constexpr long ACT_SIM  = ACT_FA + 2 * FA_PL;       // [B][S][S] row-softmaxed
constexpr long SIM_PL   = BS * Sn;
constexpr long ACT_SMT  = ACT_SIM + 2 * SIM_PL;     // [B][S][S] col-softmax^T
constexpr long SMT_PL   = BS * Sn;
constexpr long ACT_TOTAL = ACT_SMT + 2 * SMT_PL;

// ---- split weights, bf16 [N][Kpad]; lo plane at +N*Kpad
constexpr long WT_INTRA = 0;                          // 300 x 304
constexpr long WT_PROJ1 = WT_INTRA + 2L * 300 * EP;   // 200 x 600
constexpr long WT_PROJ2 = WT_PROJ1 + 2L * 120000;
constexpr long WT_ATT   = WT_PROJ2 + 2L * 120000;     // 200 x 200
constexpr long WT_CMP1  = WT_ATT + 2L * 40000;        // 400 x 400
constexpr long WT_CMP2  = WT_CMP1 + 2L * 160000;
constexpr long WT_TOTAL = WT_CMP2 + 2L * 160000;

// ---- k_gemm8 staging smem (80B rows, 2 buffers)
constexpr int SM_AH = 0;
constexpr int SM_AL = 10240;
constexpr int SM_BH = 20480;
constexpr int SM_BL = 30720;
constexpr int SM_BUF = 40960;
constexpr int SMEM8_BYTES = 2 * SM_BUF;  // 80 KB (also covers 128x129 f32)

// ---- k_gemm4 staging: 80B rows; A triple-buffered, B double-buffered
constexpr int S4_STG    = 20480;
constexpr int S4_B_BASE = 61440;
constexpr int SMEM4_BYTES = 102400;  // 100 KB -> 2 CTAs/SM

enum { EPI_STORE = 0, EPI_ATT = 1, EPI_SIM = 2, EPI_POOL = 3 };
constexpr int NO_SPLIT = 1 << 30;
}  // namespace

__device__ float g_scratch[F32_TOTAL];
__device__ __nv_bfloat16 g_act[ACT_TOTAL];
__device__ __nv_bfloat16 g_wt[WT_TOTAL];

// ---------------------------------------------------------------------------
// helpers
// ---------------------------------------------------------------------------
__device__ __forceinline__ uint32_t smem_u32(const void* p) {
    uint32_t a;
    asm("{ .reg .u64 t; cvta.to.shared.u64 t, %1; cvt.u32.u64 %0, t; }" : "=r"(a) : "l"(p));
    return a;
}
__device__ __forceinline__ void split1(float v, __nv_bfloat16& h, __nv_bfloat16& l) {
    h = __float2bfloat16(v);
    l = __float2bfloat16(v - __bfloat162float(h));
}
__device__ __forceinline__ void cp16(uint32_t dst, const void* src, int bytes) {
    asm volatile("cp.async.cg.shared.global [%0], [%1], 16, %2;"
                 :: "r"(dst), "l"(src), "r"(bytes) : "memory");
}
__device__ __forceinline__ void cp_commit() {
    asm volatile("cp.async.commit_group;" ::: "memory");
}
template <int N>
__device__ __forceinline__ void cp_wait() {
    asm volatile("cp.async.wait_group %0;" :: "n"(N) : "memory");
}
__device__ __forceinline__ void ldm_x4(uint32_t* r, uint32_t addr) {
    asm volatile("ldmatrix.sync.aligned.m8n8.x4.shared.b16 {%0,%1,%2,%3}, [%4];"
                 : "=r"(r[0]), "=r"(r[1]), "=r"(r[2]), "=r"(r[3]) : "r"(addr));
}
__device__ __forceinline__ void ldm_x2(uint32_t* r, uint32_t addr) {
    asm volatile("ldmatrix.sync.aligned.m8n8.x2.shared.b16 {%0,%1}, [%2];"
                 : "=r"(r[0]), "=r"(r[1]) : "r"(addr));
}
__device__ __forceinline__ void mma16816(float* c, const uint32_t* a, const uint32_t* b) {
    asm volatile(
        "mma.sync.aligned.m16n8k16.row.col.f32.bf16.bf16.f32 "
        "{%0,%1,%2,%3}, {%4,%5,%6,%7}, {%8,%9}, {%0,%1,%2,%3};"
        : "+f"(c[0]), "+f"(c[1]), "+f"(c[2]), "+f"(c[3])
        : "r"(a[0]), "r"(a[1]), "r"(a[2]), "r"(a[3]), "r"(b[0]), "r"(b[1]));
}

// ===========================================================================
// k_gemm8 — 8-warp (256 thread) GEMM, 2x4 warp grid, 64x32 warp tiles.
// bSameA: B tile == A tile (f@f^T) -> stage once, read B frags from A smem,
// AND exploit symmetry: warps (wm==1, wn<2) skip compute; their quadrant
// (rows 64-127 x cols 0-63) is mirrored from the transpose in the epilogue.
// ===========================================================================
template <int EPI>
__global__ void __launch_bounds__(256, 2)
k_gemm8(long offA, int lda, long sA, long planeA,
        int bMode, long offB, int ldb, long sB, long planeB,
        long offC, int ldc, long sC, long planeC,
        long offC2, long planeC2,
        int altSplit, long offAa, long offBa, long offCa,
        int Nreal, int K, int doRelu, const float* biasPtr, int bSameA) {
    extern __shared__ __align__(16) char smem[];
    const uint32_t sb0 = smem_u32(smem);
    const int tid = threadIdx.x;
    const int lane = tid & 31, wid = tid >> 5;
    const int wm = wid & 1, wn = wid >> 1;  // 2x4 warp grid -> 64x32 per warp
    const int n0 = blockIdx.x * 128, m0 = blockIdx.y * 128;
    int b = blockIdx.z;
    if (b >= altSplit) {
        b -= altSplit;
        offA = offAa; offB = offBa; offC = offCa;
    }

    const __nv_bfloat16* Ahi = g_act + offA + (long)b * sA;
    const __nv_bfloat16* Alo = Ahi + planeA;
    const __nv_bfloat16* Bhi = g_act + offB + (long)b * sB;
    const __nv_bfloat16* Blo = Bhi + planeB;

    float acc[4][4][4] = {};
    const int crow = tid >> 2, cch = tid & 3;
    const int nN = (tid & 63) * 2, nKb = tid >> 6;
    const int nChunks = (K + 31) >> 5;
    const uint32_t bOffH = bSameA ? (uint32_t)SM_AH : (uint32_t)SM_BH;
    // symmetric case: below-diagonal warp tiles are transposes of computed ones
    const bool skipWarp = (bSameA != 0) && (wm == 1) && (wn < 2);
    uint32_t pfh[8], pfl[8];

#define ISSUE_A8(c, bi)                                                         \
    {                                                                           \
        const int k0 = (c) << 5;                                                \
        _Pragma("unroll") for (int i = 0; i < 2; i++) {                         \
            int row = crow + i * 64;                                            \
            int gk = k0 + cch * 8;                                              \
            int bytes = K - gk;                                                 \
            bytes = bytes < 0 ? 0 : (bytes > 8 ? 8 : bytes);                    \
            bytes *= 2;                                                         \
            long ro = (long)(m0 + row) * lda;                                   \
            uint32_t d = sb0 + (bi)*SM_BUF + (uint32_t)(row * 80 + cch * 16);   \
            cp16(d + SM_AH, Ahi + ro + (bytes ? gk : 0), bytes);                \
            cp16(d + SM_AL, Alo + ro + (bytes ? gk : 0), bytes);                \
        }                                                                       \
    }
#define ISSUE_B8(c, bi)                                                         \
    {                                                                           \
        const int k0 = (c) << 5;                                                \
        _Pragma("unroll") for (int i = 0; i < 2; i++) {                         \
            int n = crow + i * 64;                                              \
            int gn = n0 + n;                                                    \
            int gk = k0 + cch * 8;                                              \
            int bytes = K - gk;                                                 \
            bytes = bytes < 0 ? 0 : (bytes > 8 ? 8 : bytes);                    \
            bytes *= 2;                                                         \
            if (gn >= Nreal) bytes = 0;                                         \
            long ro = bytes ? (long)gn * ldb + gk : 0;                          \
            uint32_t d = sb0 + (bi)*SM_BUF + (uint32_t)(n * 80 + cch * 16);     \
            cp16(d + SM_BH, Bhi + ro, bytes);                                   \
            cp16(d + SM_BL, Blo + ro, bytes);                                   \
        }                                                                       \
    }
#define LDGB8(c)                                                                \
    {                                                                           \
        const int k0 = (c) << 5;                                                \
        const int gn = n0 + nN;                                                 \
        const bool nin = (gn < Nreal);                                          \
        _Pragma("unroll") for (int it = 0; it < 8; it++) {                      \
            int gk = k0 + nKb + it * 4;                                         \
            if (nin && gk < K) {                                                \
                long e = (long)gk * ldb + gn;                                   \
                pfh[it] = *reinterpret_cast<const uint32_t*>(Bhi + e);          \
                pfl[it] = *reinterpret_cast<const uint32_t*>(Blo + e);          \
            } else {                                                            \
                pfh[it] = 0; pfl[it] = 0;                                       \
            }                                                                   \
        }                                                                       \
    }
#define STOREB8(bi)                                                             \
    {                                                                           \
        char* sm = smem + (bi)*SM_BUF;                                          \
        _Pragma("unroll") for (int it = 0; it < 8; it++) {                      \
            int kk = nKb + it * 4;                                              \
            __nv_bfloat162 h2 = *reinterpret_cast<__nv_bfloat162*>(&pfh[it]);   \
            __nv_bfloat162 l2 = *reinterpret_cast<__nv_bfloat162*>(&pfl[it]);   \
            *reinterpret_cast<__nv_bfloat16*>(sm + SM_BH + nN * 80 + kk * 2) = h2.x; \
            *reinterpret_cast<__nv_bfloat16*>(sm + SM_BL + nN * 80 + kk * 2) = l2.x; \
            *reinterpret_cast<__nv_bfloat16*>(sm + SM_BH + (nN + 1) * 80 + kk * 2) = h2.y; \
            *reinterpret_cast<__nv_bfloat16*>(sm + SM_BL + (nN + 1) * 80 + kk * 2) = l2.y; \
        }                                                                       \
    }

    ISSUE_A8(0, 0);
    if (bMode < 2 && !bSameA) { ISSUE_B8(0, 0); }
    cp_commit();
    if (bMode == 2) { LDGB8(0); STOREB8(0); }

    for (int c = 0; c < nChunks; c++) {
        const bool more = (c + 1 < nChunks);
        if (more) {
            ISSUE_A8(c + 1, (c + 1) & 1);
            if (bMode < 2 && !bSameA) ISSUE_B8(c + 1, (c + 1) & 1);
            cp_commit();
            if (bMode == 2) LDGB8(c + 1);
        }
        if (more) cp_wait<1>(); else cp_wait<0>();
        __syncthreads();

        if (!skipWarp) {  // warp-uniform; whole compute block skipped for mirrors
            const uint32_t sb = sb0 + (uint32_t)((c & 1) * SM_BUF);
#pragma unroll
            for (int ks = 0; ks < 2; ks++) {
                uint32_t bh[4][2], bl[4][2];
#pragma unroll
                for (int ni = 0; ni < 4; ni++) {
                    uint32_t off = (uint32_t)((wn * 32 + ni * 8 + (lane & 7)) * 80 + ks * 32 +
                                              ((lane >> 3) & 1) * 16);
                    ldm_x2(bh[ni], sb + bOffH + off);
                    ldm_x2(bl[ni], sb + bOffH + 10240 + off);
                }
#pragma unroll
                for (int mi = 0; mi < 4; mi++) {
                    uint32_t ah[4], al[4];
                    uint32_t off = (uint32_t)((wm * 64 + mi * 16 + (lane & 15)) * 80 + ks * 32 +
                                              (lane >> 4) * 16);
                    ldm_x4(ah, sb + SM_AH + off);
                    ldm_x4(al, sb + SM_AL + off);
#pragma unroll
                    for (int ni = 0; ni < 4; ni++) {
                        mma16816(acc[mi][ni], ah, bh[ni]);
                        mma16816(acc[mi][ni], ah, bl[ni]);
                        mma16816(acc[mi][ni], al, bh[ni]);
                    }
                }
            }
        }
        if (bMode == 2 && more) STOREB8((c + 1) & 1);
        __syncthreads();
    }
#undef ISSUE_A8
#undef ISSUE_B8
#undef LDGB8
#undef STOREB8

    const int trow = lane >> 2, tcol = (lane & 3) * 2;

    if constexpr (EPI == EPI_STORE) {
        __nv_bfloat16* Chi = g_act + offC + (long)b * sC;
        __nv_bfloat16* Clo = Chi + planeC;
#pragma unroll
        for (int mi = 0; mi < 4; mi++) {
            int r0 = m0 + wm * 64 + mi * 16 + trow;
#pragma unroll
            for (int ni = 0; ni < 4; ni++) {
                int c0 = n0 + wn * 32 + ni * 8 + tcol;
                if (c0 >= Nreal) continue;
                float v0 = acc[mi][ni][0], v1 = acc[mi][ni][1];
                float v2 = acc[mi][ni][2], v3 = acc[mi][ni][3];
                if (doRelu) {
                    v0 = fmaxf(v0, 0.f); v1 = fmaxf(v1, 0.f);
                    v2 = fmaxf(v2, 0.f); v3 = fmaxf(v3, 0.f);
                }
                __nv_bfloat162 h01, l01, h23, l23;
                split1(v0, h01.x, l01.x); split1(v1, h01.y, l01.y);
                split1(v2, h23.x, l23.x); split1(v3, h23.y, l23.y);
                long e0 = (long)r0 * ldc + c0, e1 = (long)(r0 + 8) * ldc + c0;
                *reinterpret_cast<__nv_bfloat162*>(Chi + e0) = h01;
                *reinterpret_cast<__nv_bfloat162*>(Clo + e0) = l01;
                *reinterpret_cast<__nv_bfloat162*>(Chi + e1) = h23;
                *reinterpret_cast<__nv_bfloat162*>(Clo + e1) = l23;
            }
        }
    } else {  // EPI_ATT / EPI_SIM
        float* smF = reinterpret_cast<float*>(smem);  // 128x129
        const float bias = (EPI == EPI_ATT) ? biasPtr[0] : 0.f;
        const float* mRow = g_scratch + OFF_MASK1 + (long)b * Sn;
        const float* mCol = g_scratch + OFF_MASK2 + (long)b * Sn;
        if (!skipWarp) {
#pragma unroll
            for (int mi = 0; mi < 4; mi++) {
                int r0 = wm * 64 + mi * 16 + trow;
#pragma unroll
                for (int ni = 0; ni < 4; ni++) {
                    int c0 = wn * 32 + ni * 8 + tcol;
                    float v0 = acc[mi][ni][0], v1 = acc[mi][ni][1];
                    float v2 = acc[mi][ni][2], v3 = acc[mi][ni][3];
                    if (EPI == EPI_ATT) {
                        v0 += (abs(r0 - c0) >= 10) ? bias : 0.f;
                        v1 += (abs(r0 - c0 - 1) >= 10) ? bias : 0.f;
                        v2 += (abs(r0 + 8 - c0) >= 10) ? bias : 0.f;
                        v3 += (abs(r0 + 8 - c0 - 1) >= 10) ? bias : 0.f;
                    } else {
                        float rm0 = mRow[r0], rm1 = mRow[r0 + 8];
                        float cm0 = mCol[c0], cm1 = mCol[c0 + 1];
                        v0 *= rm0 * cm0; v1 *= rm0 * cm1;
                        v2 *= rm1 * cm0; v3 *= rm1 * cm1;
                    }
                    smF[r0 * 129 + c0] = v0;
                    smF[r0 * 129 + c0 + 1] = v1;
                    smF[(r0 + 8) * 129 + c0] = v2;
                    smF[(r0 + 8) * 129 + c0 + 1] = v3;
                }
            }
        }
        __syncthreads();
        if (EPI == EPI_ATT && bSameA) {
            // mirror missing quadrant (rows 64-127 x cols 0-63) from transpose
            for (int idx = tid; idx < 64 * 64; idx += 256) {
                int r = 64 + (idx >> 6), c = idx & 63;
                smF[r * 129 + c] = smF[c * 129 + r];
            }
            __syncthreads();
        }
        {
            __nv_bfloat16* Chi = g_act + offC + (long)b * sC;
            __nv_bfloat16* Clo = Chi + planeC;
            for (int r = wid; r < 128; r += 8) {
                float v[4];
                float mx = -1e30f;
#pragma unroll
                for (int k = 0; k < 4; k++) {
                    v[k] = smF[r * 129 + lane + k * 32];
                    mx = fmaxf(mx, v[k]);
                }
#pragma unroll
                for (int o = 16; o; o >>= 1) mx = fmaxf(mx, __shfl_xor_sync(0xffffffffu, mx, o));
                float s = 0.f;
#pragma unroll
                for (int k = 0; k < 4; k++) {
                    v[k] = expf(v[k] - mx);
                    s += v[k];
                }
#pragma unroll
                for (int o = 16; o; o >>= 1) s += __shfl_xor_sync(0xffffffffu, s, o);
                float inv = 1.0f / s;
#pragma unroll
                for (int k = 0; k < 4; k++) {
                    __nv_bfloat16 h, l;
                    split1(v[k] * inv, h, l);
                    long e = (long)r * Sn + lane + k * 32;
                    Chi[e] = h;
                    Clo[e] = l;
                }
            }
        }
        if constexpr (EPI == EPI_SIM) {
            __nv_bfloat16* C2hi = g_act + offC2 + (long)b * sC;
            __nv_bfloat16* C2lo = C2hi + planeC2;
            for (int c = wid; c < 128; c += 8) {
                float v[4];
                float mx = -1e30f;
#pragma unroll
                for (int k = 0; k < 4; k++) {
                    v[k] = smF[(lane + k * 32) * 129 + c];
                    mx = fmaxf(mx, v[k]);
                }
#pragma unroll
                for (int o = 16; o; o >>= 1) mx = fmaxf(mx, __shfl_xor_sync(0xffffffffu, mx, o));
                float s = 0.f;
#pragma unroll
                for (int k = 0; k < 4; k++) {
                    v[k] = expf(v[k] - mx);
                    s += v[k];
                }
#pragma unroll
                for (int o = 16; o; o >>= 1) s += __shfl_xor_sync(0xffffffffu, s, o);
                float inv = 1.0f / s;
#pragma unroll
                for (int k = 0; k < 4; k++) {
                    __nv_bfloat16 h, l;
                    split1(v[k] * inv, h, l);
                    long e = (long)c * Sn + lane + k * 32;
                    C2hi[e] = h;
                    C2lo[e] = l;
                }
            }
        }
    }
}

// ===========================================================================
// k_gemm4 — 4-warp (128 thread) GEMM.  (R13/R14-proven)
// WN=2: 2x2 warp grid, 64x64 warp tiles, CTA tile 128 cols.
// WN=1: 4x1 warp grid, CTA tile 64 cols (N-edge variant).
// A triple-buffered / B double-buffered cp.async pipeline, 80B rows.
// ===========================================================================
template <int EPI, int WN>
__global__ void __launch_bounds__(128, 2)
k_gemm4(long offA, int lda, long sA, long planeA,
        long offB, int ldb, long sB, long planeB,
        long offC, int ldc, long sC, long planeC,
        int n0base, int Nreal, int K, int doRelu) {
    constexpr int MI = (WN == 2) ? 4 : 2;
    constexpr int NT = WN * 64;
    constexpr int WMC = 4 / WN;
    extern __shared__ __align__(16) char smem[];
    const uint32_t sb0 = smem_u32(smem);
    const int tid = threadIdx.x;
    const int lane = tid & 31, wid = tid >> 5;
    const int wm = (WN == 2) ? (wid & 1) : wid;
    const int wn = (WN == 2) ? (wid >> 1) : 0;
    const int n0 = n0base + blockIdx.x * NT;
    const int m0 = blockIdx.y * 128;
    const int b = blockIdx.z;

    const __nv_bfloat16* Ahi = g_act + offA + (long)b * sA;
    const __nv_bfloat16* Alo = Ahi + planeA;
    const __nv_bfloat16* Bhi = g_wt + offB + (long)b * sB;
    const __nv_bfloat16* Blo = Bhi + planeB;

    float acc[MI][8][4] = {};
    const int crow = tid >> 2, cch = tid & 3;
    const int nChunks = (K + 31) >> 5;

#define ISSUE_A4(c, stg)                                                        \
    {                                                                           \
        const int k0 = (c) << 5;                                                \
        const int gk = k0 + cch * 8;                                            \
        int bytes = K - gk;                                                     \
        bytes = bytes < 0 ? 0 : (bytes > 8 ? 8 : bytes);                        \
        bytes *= 2;                                                             \
        _Pragma("unroll") for (int i = 0; i < 4; i++) {                         \
            int row = crow + i * 32;                                            \
            long ro = (long)(m0 + row) * lda;                                   \
            uint32_t d = sb0 + (stg)*S4_STG + (uint32_t)(row * 80 + cch * 16);  \
            cp16(d, Ahi + ro + (bytes ? gk : 0), bytes);                        \
            cp16(d + 10240, Alo + ro + (bytes ? gk : 0), bytes);                \
        }                                                                       \
    }
#define ISSUE_B4(c, stg)                                                        \
    {                                                                           \
        const int k0 = (c) << 5;                                                \
        const int gk = k0 + cch * 8;                                            \
        int kb = K - gk;                                                        \
        kb = kb < 0 ? 0 : (kb > 8 ? 8 : kb);                                    \
        kb *= 2;                                                                \
        _Pragma("unroll") for (int i = 0; i < NT / 32; i++) {                   \
            int n = crow + i * 32;                                              \
            int gn = n0 + n;                                                    \
            int bytes = (gn < Nreal) ? kb : 0;                                  \
            long ro = bytes ? (long)gn * ldb + gk : 0;                          \
            uint32_t d = sb0 + S4_B_BASE + (stg)*S4_STG +                       \
                         (uint32_t)(n * 80 + cch * 16);                         \
            cp16(d, Bhi + ro, bytes);                                           \
            cp16(d + 10240, Blo + ro, bytes);                                   \
        }                                                                       \
    }

    ISSUE_A4(0, 0);
    if (1 < nChunks) ISSUE_A4(1, 1);
    ISSUE_B4(0, 0);
    cp_commit();
    if (2 < nChunks) ISSUE_A4(2, 2);
    if (1 < nChunks) ISSUE_B4(1, 1);
    cp_commit();

    for (int c = 0; c < nChunks; c++) {
        cp_wait<1>();
        __syncthreads();

        const uint32_t sa = sb0 + (uint32_t)((c % 3) * S4_STG);
        const uint32_t sbb = sb0 + (uint32_t)(S4_B_BASE + (c & 1) * S4_STG);
#pragma unroll
        for (int ks = 0; ks < 2; ks++) {
            uint32_t bh[8][2], bl[8][2];
#pragma unroll
            for (int p = 0; p < 4; p++) {
                uint32_t row = (uint32_t)(wn * 64 + p * 16 + ((lane >> 4) << 3) + (lane & 7));
                uint32_t off = row * 80 + (uint32_t)(ks * 32 + ((lane >> 3) & 1) * 16);
                uint32_t r4[4];
                ldm_x4(r4, sbb + off);
                bh[2 * p][0] = r4[0]; bh[2 * p][1] = r4[1];
                bh[2 * p + 1][0] = r4[2]; bh[2 * p + 1][1] = r4[3];
                ldm_x4(r4, sbb + 10240 + off);
                bl[2 * p][0] = r4[0]; bl[2 * p][1] = r4[1];
                bl[2 * p + 1][0] = r4[2]; bl[2 * p + 1][1] = r4[3];
            }
#pragma unroll
            for (int mi = 0; mi < MI; mi++) {
                uint32_t ah[4], al[4];
                uint32_t off = (uint32_t)((wm * (MI * 16) + mi * 16 + (lane & 15)) * 80 +
                                          ks * 32 + (lane >> 4) * 16);
                ldm_x4(ah, sa + off);
                ldm_x4(al, sa + 10240 + off);
#pragma unroll
                for (int ni = 0; ni < 8; ni++) {
                    mma16816(acc[mi][ni], ah, bh[ni]);
                    mma16816(acc[mi][ni], ah, bl[ni]);
                    mma16816(acc[mi][ni], al, bh[ni]);
                }
            }
        }
        __syncthreads();
        if (c + 3 < nChunks) ISSUE_A4(c + 3, (c + 3) % 3);
        if (c + 2 < nChunks) ISSUE_B4(c + 2, (c + 2) & 1);
        cp_commit();
    }
#undef ISSUE_A4
#undef ISSUE_B4

    const int trow = lane >> 2, tcol = (lane & 3) * 2;

    if constexpr (EPI == EPI_STORE) {
        __nv_bfloat16* Chi = g_act + offC + (long)b * sC;
        __nv_bfloat16* Clo = Chi + planeC;
#pragma unroll
        for (int mi = 0; mi < MI; mi++) {
            int r0 = m0 + wm * (MI * 16) + mi * 16 + trow;
#pragma unroll
            for (int ni = 0; ni < 8; ni++) {
                int c0 = n0 + wn * 64 + ni * 8 + tcol;
                if (c0 >= Nreal) continue;
                float v0 = acc[mi][ni][0], v1 = acc[mi][ni][1];
                float v2 = acc[mi][ni][2], v3 = acc[mi][ni][3];
                if (doRelu) {
                    v0 = fmaxf(v0, 0.f); v1 = fmaxf(v1, 0.f);
                    v2 = fmaxf(v2, 0.f); v3 = fmaxf(v3, 0.f);
                }
                __nv_bfloat162 h01, l01, h23, l23;
                split1(v0, h01.x, l01.x); split1(v1, h01.y, l01.y);
                split1(v2, h23.x, l23.x); split1(v3, h23.y, l23.y);
                long e0 = (long)r0 * ldc + c0, e1 = (long)(r0 + 8) * ldc + c0;
                *reinterpret_cast<__nv_bfloat162*>(Chi + e0) = h01;
                *reinterpret_cast<__nv_bfloat162*>(Clo + e0) = l01;
                *reinterpret_cast<__nv_bfloat162*>(Chi + e1) = h23;
                *reinterpret_cast<__nv_bfloat162*>(Clo + e1) = l23;
            }
        }
    } else {  // EPI_POOL
        const int side = blockIdx.z;
        const float* mask = g_scratch + (side ? OFF_MASK2 : OFF_MASK1) + (long)blockIdx.y * Sn;
        float* smP = reinterpret_cast<float*>(smem);  // [WMC][NT]
        float p[8][2];
#pragma unroll
        for (int ni = 0; ni < 8; ni++) { p[ni][0] = 0.f; p[ni][1] = 0.f; }
#pragma unroll
        for (int mi = 0; mi < MI; mi++) {
            int r0 = wm * (MI * 16) + mi * 16 + trow;
            float m0v = mask[r0], m1v = mask[r0 + 8];
#pragma unroll
            for (int ni = 0; ni < 8; ni++) {
                p[ni][0] += fmaxf(acc[mi][ni][0], 0.f) * m0v + fmaxf(acc[mi][ni][2], 0.f) * m1v;
                p[ni][1] += fmaxf(acc[mi][ni][1], 0.f) * m0v + fmaxf(acc[mi][ni][3], 0.f) * m1v;
            }
        }
#pragma unroll
        for (int ni = 0; ni < 8; ni++) {
#pragma unroll
            for (int o = 4; o <= 16; o <<= 1) {
                p[ni][0] += __shfl_xor_sync(0xffffffffu, p[ni][0], o);
                p[ni][1] += __shfl_xor_sync(0xffffffffu, p[ni][1], o);
            }
        }
        __syncthreads();
        if (lane < 4) {
#pragma unroll
            for (int ni = 0; ni < 8; ni++) {
                smP[wm * NT + wn * 64 + ni * 8 + lane * 2] = p[ni][0];
                smP[wm * NT + wn * 64 + ni * 8 + lane * 2 + 1] = p[ni][1];
            }
        }
        __syncthreads();
        if (tid < NT) {
            int gcol = n0 + tid;
            if (gcol < Nreal) {
                float s = 0.f;
#pragma unroll
                for (int w = 0; w < WMC; w++) s += smP[w * NT + tid];
                g_scratch[OFF_POOL + (long)blockIdx.y * 800 + (long)side * 400 + gcol] = s;
            }
        }
    }
}

// ---------------------------------------------------------------------------
// All weights: transpose + split, one launch. W [K][N] f32 -> [N][Kp] hi/lo
// ---------------------------------------------------------------------------
__global__ void k_wsplit_all(const float* __restrict__ w_intra,
                             const float* __restrict__ w_proj1,
                             const float* __restrict__ w_proj2,
                             const float* __restrict__ w_att,
                             const float* __restrict__ w_cmp1,
                             const float* __restrict__ w_cmp2) {
    const float* W;
    int K, N, Kp;
    long off;
    switch (blockIdx.y) {
        case 0: W = w_intra; K = En;     N = En;     Kp = EP;     off = WT_INTRA; break;
        case 1: W = w_proj1; K = 2 * En; N = Pn;     Kp = 2 * En; off = WT_PROJ1; break;
        case 2: W = w_proj2; K = 2 * En; N = Pn;     Kp = 2 * En; off = WT_PROJ2; break;
        case 3: W = w_att;   K = Pn;     N = Pn;     Kp = Pn;     off = WT_ATT;   break;
        case 4: W = w_cmp1;  K = 2 * Pn; N = 2 * Pn; Kp = 2 * Pn; off = WT_CMP1;  break;
        default: W = w_cmp2; K = 2 * Pn; N = 2 * Pn; Kp = 2 * Pn; off = WT_CMP2;  break;
    }
    long total = (long)K * N;
    long plane = (long)N * Kp;
    for (long i = (long)blockIdx.x * blockDim.x + threadIdx.x; i < total;
         i += (long)gridDim.x * blockDim.x) {
        int n = (int)(i / K), k = (int)(i % K);
        float v = W[(long)k * N + n];
        __nv_bfloat16 h, l;
        split1(v, h, l);
        g_wt[off + (long)n * Kp + k] = h;
        g_wt[off + plane + (long)n * Kp + k] = l;
    }
}

// ---------------------------------------------------------------------------
// Non-GEMM kernels
// ---------------------------------------------------------------------------
__global__ void k_seqmask(const int* __restrict__ x1, const int* __restrict__ x2) {
    int b = blockIdx.x;
    const int* x = blockIdx.y ? x2 : x1;
    float* m = g_scratch + (blockIdx.y ? OFF_MASK2 : OFF_MASK1);
    int t = threadIdx.x;
    int nz = __syncthreads_count(x[b * Sn + t] != 0);
    m[b * Sn + t] = (t < nz) ? 1.0f : 0.0f;
}

__global__ void k_gather(const int* __restrict__ x1, const int* __restrict__ x2,
                         const float* __restrict__ emb) {
    int side = blockIdx.y;
    const int* x = side ? x2 : x1;
    int lane = threadIdx.x & 31;
    long bs = (long)blockIdx.x * 8 + (threadIdx.x >> 5);
    int row = x[bs];
    const float* e = emb + (long)row * En;
    float v[10];
    float ss = 0.f;
#pragma unroll
    for (int i = 0; i < 10; i++) {
        int idx = lane + i * 32;
        v[i] = (idx < En) ? e[idx] : 0.f;
        ss += v[i] * v[i];
    }
#pragma unroll
    for (int o = 16; o; o >>= 1) ss += __shfl_xor_sync(0xffffffffu, ss, o);
    float inv = 1.0f / sqrtf(fmaxf(ss, 1e-12f));
    __nv_bfloat16* hi = g_act + ACT_CAT + (long)side * BS * 600 + bs * 600;
    __nv_bfloat16* lo = hi + CAT_PL;
#pragma unroll
    for (int i = 0; i < 10; i++) {
        int idx = lane + i * 32;
        if (idx < En) {
            __nv_bfloat16 h, l;
            split1(v[i] * inv, h, l);
            hi[idx] = h;
            lo[idx] = l;
        }
    }
}

__global__ void k_final(const float* __restrict__ w_agg, float* __restrict__ out) {
    int b = blockIdx.x;
    int tid = threadIdx.x;
    int c = tid >> 5, lane = tid & 31;
    const float* p = g_scratch + OFF_POOL + (long)b * 800;
    float acc = 0.f;
    for (int n = lane; n < 800; n += 32) acc += p[n] * w_agg[n * Cn + c];
#pragma unroll
    for (int o = 16; o; o >>= 1) acc += __shfl_xor_sync(0xffffffffu, acc, o);
    if (lane == 0) out[b * Cn + c] = fmaxf(acc, 0.f);
}

// ---------------------------------------------------------------------------
// Orchestration
// ---------------------------------------------------------------------------
extern "C" void kernel_launch(void* const* d_in, const int* in_sizes, int n_in,
                              void* d_out, int out_size) {
    const int* x1 = (const int*)d_in[0];
    const int* x2 = (const int*)d_in[1];
    const float* emb = (const float*)d_in[2];
    const float* w_intra = (const float*)d_in[3];
    const float* bias_intra = (const float*)d_in[4];
    const float* w_proj1 = (const float*)d_in[5];
    const float* w_proj2 = (const float*)d_in[6];
    const float* w_att = (const float*)d_in[7];
    const float* w_cmp1 = (const float*)d_in[8];
    const float* w_cmp2 = (const float*)d_in[9];
    const float* w_agg = (const float*)d_in[10];
    float* out = (float*)d_out;

    cudaFuncSetAttribute(k_gemm8<EPI_STORE>, cudaFuncAttributeMaxDynamicSharedMemorySize, SMEM8_BYTES);
    cudaFuncSetAttribute(k_gemm8<EPI_ATT>, cudaFuncAttributeMaxDynamicSharedMemorySize, SMEM8_BYTES);
    cudaFuncSetAttribute(k_gemm8<EPI_SIM>, cudaFuncAttributeMaxDynamicSharedMemorySize, SMEM8_BYTES);
    cudaFuncSetAttribute((const void*)k_gemm4<EPI_STORE, 2>, cudaFuncAttributeMaxDynamicSharedMemorySize, SMEM4_BYTES);
    cudaFuncSetAttribute((const void*)k_gemm4<EPI_STORE, 1>, cudaFuncAttributeMaxDynamicSharedMemorySize, SMEM4_BYTES);
    cudaFuncSetAttribute((const void*)k_gemm4<EPI_POOL, 2>, cudaFuncAttributeMaxDynamicSharedMemorySize, SMEM4_BYTES);
    cudaFuncSetAttribute((const void*)k_gemm4<EPI_POOL, 1>, cudaFuncAttributeMaxDynamicSharedMemorySize, SMEM4_BYTES);

    k_seqmask<<<dim3(Bn, 2), Sn>>>(x1, x2);
    k_gather<<<dim3((unsigned)(BS / 8), 2), 256>>>(x1, x2, emb);
    k_wsplit_all<<<dim3(160, 6), 256>>>(w_intra, w_proj1, w_proj2, w_att, w_cmp1, w_cmp2);

    // f = relu(e @ w_intra): bulk 2 full tiles + 64-wide edge (N=300)
    k_gemm4<EPI_STORE, 2><<<dim3(2, 256, 2), 128, SMEM4_BYTES>>>(
        ACT_CAT, 600, BS * 600, CAT_PL,
        WT_INTRA, EP, 0, 300L * EP,
        ACT_F, EP, BS * EP, F_PL,
        0, En, En, 1);
    k_gemm4<EPI_STORE, 1><<<dim3(1, 256, 2), 128, SMEM4_BYTES>>>(
        ACT_CAT, 600, BS * 600, CAT_PL,
        WT_INTRA, EP, 0, 300L * EP,
        ACT_F, EP, BS * EP, F_PL,
        256, En, En, 1);

    // att = softmax_rows(f@f^T + dbias): symmetric (B == A tile, mirror quadrant)
    k_gemm8<EPI_ATT><<<dim3(1, 1, 2 * Bn), 256, SMEM8_BYTES>>>(
        ACT_F, EP, (long)Sn * EP, F_PL,
        1, ACT_F, EP, (long)Sn * EP, F_PL,
        ACT_ATT, Sn, (long)Sn * Sn, ATT_PL, 0, 0,
        NO_SPLIT, 0, 0, 0,
        Sn, En, 0, bias_intra, 1);

    // xp[g] = att[g] @ e[g]: B N-major -> cat cols 300:600
    k_gemm8<EPI_STORE><<<dim3(3, 1, 2 * Bn), 256, SMEM8_BYTES>>>(
        ACT_ATT, Sn, (long)Sn * Sn, ATT_PL,
        2, ACT_CAT, 600, (long)Sn * 600, CAT_PL,
        ACT_CAT + En, 600, (long)Sn * 600, CAT_PL, 0, 0,
        NO_SPLIT, 0, 0, 0,
        En, Sn, 0, nullptr, 0);

    // x_proj = relu(cat @ w_proj{1,2}): [2 x BS x 200], K=600
    k_gemm4<EPI_STORE, 2><<<dim3(2, 256, 2), 128, SMEM4_BYTES>>>(
        ACT_CAT, 600, BS * 600, CAT_PL,
        WT_PROJ1, 600, WT_PROJ2 - WT_PROJ1, 120000,
        ACT_CATP, 400, BS * 400, CATP_PL,
        0, Pn, 2 * En, 1);

    // fa = relu(x_proj @ w_att): [2 x BS x 200], K=200
    k_gemm4<EPI_STORE, 2><<<dim3(2, 256, 2), 128, SMEM4_BYTES>>>(
        ACT_CATP, 400, BS * 400, CATP_PL,
        WT_ATT, Pn, 0, 40000,
        ACT_FA, Pn, BS * Pn, FA_PL,
        0, Pn, Pn, 1);

    // sim: fused mask + row softmax (-> SIM) + col softmax^T (-> SMT)
    k_gemm8<EPI_SIM><<<dim3(1, 1, Bn), 256, SMEM8_BYTES>>>(
        ACT_FA, Pn, (long)Sn * Pn, FA_PL,
        1, ACT_FA + BS * Pn, Pn, (long)Sn * Pn, FA_PL,
        ACT_SIM, Sn, (long)Sn * Sn, SIM_PL,
        ACT_SMT, SMT_PL,
        NO_SPLIT, 0, 0, 0,
        Sn, Pn, 0, nullptr, 0);

    // beta (z<256) and alpha (z>=256) merged
    k_gemm8<EPI_STORE><<<dim3(2, 1, 2 * Bn), 256, SMEM8_BYTES>>>(
        ACT_SIM, Sn, (long)Sn * Sn, SIM_PL,
        2, ACT_CATP + BS * 400, 400, (long)Sn * 400, CATP_PL,
        ACT_CATP + Pn, 400, (long)Sn * 400, CATP_PL, 0, 0,
        Bn, ACT_SMT, ACT_CATP, ACT_CATP + BS * 400 + Pn,
        Pn, Sn, 0, nullptr, 0);

    // v = relu([xp|attend] @ w_cmp{1,2}) + pooling: bulk 3 tiles + 64-wide edge
    k_gemm4<EPI_POOL, 2><<<dim3(3, 256, 2), 128, SMEM4_BYTES>>>(
        ACT_CATP, 400, BS * 400, CATP_PL,
        WT_CMP1, 2 * Pn, WT_CMP2 - WT_CMP1, 160000,
        0, 0, 0, 0,
        0, 2 * Pn, 2 * Pn, 1);
    k_gemm4<EPI_POOL, 1><<<dim3(1, 256, 2), 128, SMEM4_BYTES>>>(
        ACT_CATP, 400, BS * 400, CATP_PL,
        WT_CMP1, 2 * Pn, WT_CMP2 - WT_CMP1, 160000,
        0, 0, 0, 0,
        384, 2 * Pn, 2 * Pn, 1);

    k_final<<<Bn, 96>>>(w_agg, out);
}

// round 16
// speedup vs baseline: 1.0116x; 1.0116x over previous
#include <cuda_runtime.h>
#include <cuda_bf16.h>
#include <math.h>
#include <stdint.h>

// ---------------------------------------------------------------------------
// Problem constants
// ---------------------------------------------------------------------------
namespace {
constexpr int Bn = 256, Sn = 128, En = 300, Pn = 200, Cn = 3;
constexpr long BS = (long)Bn * Sn;  // 32768
constexpr int EP = 304;             // 300 padded to 16B multiple

// ---- f32 scratch (masks + pool)
constexpr long OFF_MASK1 = 0;
constexpr long OFF_MASK2 = OFF_MASK1 + BS;
constexpr long OFF_POOL  = OFF_MASK2 + BS;
constexpr long F32_TOTAL = OFF_POOL + (long)Bn * 4 * Pn;

// ---- bf16 activation arena: every tensor is two planes (hi, lo = +PLANE)
constexpr long ACT_CAT  = 0;                        // [2][BS][600]
constexpr long CAT_PL   = 2 * BS * 600;
constexpr long ACT_F    = ACT_CAT + 2 * CAT_PL;     // [2*BS][304]
constexpr long F_PL     = 2 * BS * EP;
constexpr long ACT_ATT  = ACT_F + 2 * F_PL;         // [2*B][S][S] (softmaxed)
constexpr long ATT_PL   = 2 * BS * Sn;
constexpr long ACT_CATP = ACT_ATT + 2 * ATT_PL;     // [2][BS][400]
constexpr long CATP_PL  = 2 * BS * 2 * Pn;
constexpr long ACT_FA   = ACT_CATP + 2 * CATP_PL;   // [2][BS][200]
constexpr long FA_PL    = 2 * BS * Pn;
constexpr long ACT_SIM  = ACT_FA + 2 * FA_PL;       // [B][S][S] row-softmaxed
constexpr long SIM_PL   = BS * Sn;
constexpr long ACT_SMT  = ACT_SIM + 2 * SIM_PL;     // [B][S][S] col-softmax^T
constexpr long SMT_PL   = BS * Sn;
constexpr long ACT_TOTAL = ACT_SMT + 2 * SMT_PL;

// ---- split weights, bf16 [N][Kpad]; lo plane at +N*Kpad
constexpr long WT_INTRA = 0;                          // 300 x 304
constexpr long WT_PROJ1 = WT_INTRA + 2L * 300 * EP;   // 200 x 600
constexpr long WT_PROJ2 = WT_PROJ1 + 2L * 120000;
constexpr long WT_ATT   = WT_PROJ2 + 2L * 120000;     // 200 x 200
constexpr long WT_CMP1  = WT_ATT + 2L * 40000;        // 400 x 400
constexpr long WT_CMP2  = WT_CMP1 + 2L * 160000;
constexpr long WT_TOTAL = WT_CMP2 + 2L * 160000;

// ---- k_gemm8 staging smem (80B rows, 2 buffers)
constexpr int SM_AH = 0;
constexpr int SM_AL = 10240;
constexpr int SM_BH = 20480;
constexpr int SM_BL = 30720;
constexpr int SM_BUF = 40960;
constexpr int SMEM8_BYTES = 2 * SM_BUF;  // 80 KB (also covers 128x129 f32)

// ---- k_gemm4 staging: 80B rows; A triple-buffered, B double-buffered
constexpr int S4_STG    = 20480;
constexpr int S4_B_BASE = 61440;
constexpr int SMEM4_BYTES = 102400;  // 100 KB -> 2 CTAs/SM

enum { EPI_STORE = 0, EPI_ATT = 1, EPI_SIM = 2, EPI_POOL = 3 };
constexpr int NO_SPLIT = 1 << 30;
}  // namespace

__device__ float g_scratch[F32_TOTAL];
__device__ __nv_bfloat16 g_act[ACT_TOTAL];
__device__ __nv_bfloat16 g_wt[WT_TOTAL];

// ---------------------------------------------------------------------------
// helpers
// ---------------------------------------------------------------------------
__device__ __forceinline__ uint32_t smem_u32(const void* p) {
    uint32_t a;
    asm("{ .reg .u64 t; cvta.to.shared.u64 t, %1; cvt.u32.u64 %0, t; }" : "=r"(a) : "l"(p));
    return a;
}
__device__ __forceinline__ void split1(float v, __nv_bfloat16& h, __nv_bfloat16& l) {
    h = __float2bfloat16(v);
    l = __float2bfloat16(v - __bfloat162float(h));
}
__device__ __forceinline__ void cp16(uint32_t dst, const void* src, int bytes) {
    asm volatile("cp.async.cg.shared.global [%0], [%1], 16, %2;"
                 :: "r"(dst), "l"(src), "r"(bytes) : "memory");
}
__device__ __forceinline__ void cp_commit() {
    asm volatile("cp.async.commit_group;" ::: "memory");
}
template <int N>
__device__ __forceinline__ void cp_wait() {
    asm volatile("cp.async.wait_group %0;" :: "n"(N) : "memory");
}
__device__ __forceinline__ void ldm_x4(uint32_t* r, uint32_t addr) {
    asm volatile("ldmatrix.sync.aligned.m8n8.x4.shared.b16 {%0,%1,%2,%3}, [%4];"
                 : "=r"(r[0]), "=r"(r[1]), "=r"(r[2]), "=r"(r[3]) : "r"(addr));
}
__device__ __forceinline__ void ldm_x2(uint32_t* r, uint32_t addr) {
    asm volatile("ldmatrix.sync.aligned.m8n8.x2.shared.b16 {%0,%1}, [%2];"
                 : "=r"(r[0]), "=r"(r[1]) : "r"(addr));
}
__device__ __forceinline__ void mma16816(float* c, const uint32_t* a, const uint32_t* b) {
    asm volatile(
        "mma.sync.aligned.m16n8k16.row.col.f32.bf16.bf16.f32 "
        "{%0,%1,%2,%3}, {%4,%5,%6,%7}, {%8,%9}, {%0,%1,%2,%3};"
        : "+f"(c[0]), "+f"(c[1]), "+f"(c[2]), "+f"(c[3])
        : "r"(a[0]), "r"(a[1]), "r"(a[2]), "r"(a[3]), "r"(b[0]), "r"(b[1]));
}

// ===========================================================================
// k_gemm8 — 8-warp (256 thread) GEMM, 2x4 warp grid, 64x32 warp tiles.
// bSameA: B tile == A tile (f@f^T) -> stage once, read B frags from A smem,
// skip the 2 below-diagonal warp tiles (mirrored in epilogue). The warp->tile
// map flips with blockIdx.z parity so co-resident CTAs idle DIFFERENT SMSPs.
// ===========================================================================
template <int EPI>
__global__ void __launch_bounds__(256, 2)
k_gemm8(long offA, int lda, long sA, long planeA,
        int bMode, long offB, int ldb, long sB, long planeB,
        long offC, int ldc, long sC, long planeC,
        long offC2, long planeC2,
        int altSplit, long offAa, long offBa, long offCa,
        int Nreal, int K, int doRelu, const float* biasPtr, int bSameA) {
    extern __shared__ __align__(16) char smem[];
    const uint32_t sb0 = smem_u32(smem);
    const int tid = threadIdx.x;
    const int lane = tid & 31, wid = tid >> 5;
    // parity-balanced warp->tile map for the symmetric case
    const int swapm = (bSameA != 0) ? (int)(blockIdx.z & 1) : 0;
    const int wm = (wid & 1) ^ swapm, wn = wid >> 1;  // 2x4 grid -> 64x32 tiles
    const int n0 = blockIdx.x * 128, m0 = blockIdx.y * 128;
    int b = blockIdx.z;
    if (b >= altSplit) {
        b -= altSplit;
        offA = offAa; offB = offBa; offC = offCa;
    }

    const __nv_bfloat16* Ahi = g_act + offA + (long)b * sA;
    const __nv_bfloat16* Alo = Ahi + planeA;
    const __nv_bfloat16* Bhi = g_act + offB + (long)b * sB;
    const __nv_bfloat16* Blo = Bhi + planeB;

    float acc[4][4][4] = {};
    const int crow = tid >> 2, cch = tid & 3;
    const int nN = (tid & 63) * 2, nKb = tid >> 6;
    const int nChunks = (K + 31) >> 5;
    const uint32_t bOffH = bSameA ? (uint32_t)SM_AH : (uint32_t)SM_BH;
    // symmetric case: below-diagonal warp tiles are transposes of computed ones
    const bool skipWarp = (bSameA != 0) && (wm == 1) && (wn < 2);
    uint32_t pfh[8], pfl[8];

#define ISSUE_A8(c, bi)                                                         \
    {                                                                           \
        const int k0 = (c) << 5;                                                \
        _Pragma("unroll") for (int i = 0; i < 2; i++) {                         \
            int row = crow + i * 64;                                            \
            int gk = k0 + cch * 8;                                              \
            int bytes = K - gk;                                                 \
            bytes = bytes < 0 ? 0 : (bytes > 8 ? 8 : bytes);                    \
            bytes *= 2;                                                         \
            long ro = (long)(m0 + row) * lda;                                   \
            uint32_t d = sb0 + (bi)*SM_BUF + (uint32_t)(row * 80 + cch * 16);   \
            cp16(d + SM_AH, Ahi + ro + (bytes ? gk : 0), bytes);                \
            cp16(d + SM_AL, Alo + ro + (bytes ? gk : 0), bytes);                \
        }                                                                       \
    }
#define ISSUE_B8(c, bi)                                                         \
    {                                                                           \
        const int k0 = (c) << 5;                                                \
        _Pragma("unroll") for (int i = 0; i < 2; i++) {                         \
            int n = crow + i * 64;                                              \
            int gn = n0 + n;                                                    \
            int gk = k0 + cch * 8;                                              \
            int bytes = K - gk;                                                 \
            bytes = bytes < 0 ? 0 : (bytes > 8 ? 8 : bytes);                    \
            bytes *= 2;                                                         \
            if (gn >= Nreal) bytes = 0;                                         \
            long ro = bytes ? (long)gn * ldb + gk : 0;                          \
            uint32_t d = sb0 + (bi)*SM_BUF + (uint32_t)(n * 80 + cch * 16);     \
            cp16(d + SM_BH, Bhi + ro, bytes);                                   \
            cp16(d + SM_BL, Blo + ro, bytes);                                   \
        }                                                                       \
    }
#define LDGB8(c)                                                                \
    {                                                                           \
        const int k0 = (c) << 5;                                                \
        const int gn = n0 + nN;                                                 \
        const bool nin = (gn < Nreal);                                          \
        _Pragma("unroll") for (int it = 0; it < 8; it++) {                      \
            int gk = k0 + nKb + it * 4;                                         \
            if (nin && gk < K) {                                                \
                long e = (long)gk * ldb + gn;                                   \
                pfh[it] = *reinterpret_cast<const uint32_t*>(Bhi + e);          \
                pfl[it] = *reinterpret_cast<const uint32_t*>(Blo + e);          \
            } else {                                                            \
                pfh[it] = 0; pfl[it] = 0;                                       \
            }                                                                   \
        }                                                                       \
    }
#define STOREB8(bi)                                                             \
    {                                                                           \
        char* sm = smem + (bi)*SM_BUF;                                          \
        _Pragma("unroll") for (int it = 0; it < 8; it++) {                      \
            int kk = nKb + it * 4;                                              \
            __nv_bfloat162 h2 = *reinterpret_cast<__nv_bfloat162*>(&pfh[it]);   \
            __nv_bfloat162 l2 = *reinterpret_cast<__nv_bfloat162*>(&pfl[it]);   \
            *reinterpret_cast<__nv_bfloat16*>(sm + SM_BH + nN * 80 + kk * 2) = h2.x; \
            *reinterpret_cast<__nv_bfloat16*>(sm + SM_BL + nN * 80 + kk * 2) = l2.x; \
            *reinterpret_cast<__nv_bfloat16*>(sm + SM_BH + (nN + 1) * 80 + kk * 2) = h2.y; \
            *reinterpret_cast<__nv_bfloat16*>(sm + SM_BL + (nN + 1) * 80 + kk * 2) = l2.y; \
        }                                                                       \
    }

    ISSUE_A8(0, 0);
    if (bMode < 2 && !bSameA) { ISSUE_B8(0, 0); }
    cp_commit();
    if (bMode == 2) { LDGB8(0); STOREB8(0); }

    for (int c = 0; c < nChunks; c++) {
        const bool more = (c + 1 < nChunks);
        if (more) {
            ISSUE_A8(c + 1, (c + 1) & 1);
            if (bMode < 2 && !bSameA) ISSUE_B8(c + 1, (c + 1) & 1);
            cp_commit();
            if (bMode == 2) LDGB8(c + 1);
        }
        if (more) cp_wait<1>(); else cp_wait<0>();
        __syncthreads();

        if (!skipWarp) {  // warp-uniform; whole compute block skipped for mirrors
            const uint32_t sb = sb0 + (uint32_t)((c & 1) * SM_BUF);
#pragma unroll
            for (int ks = 0; ks < 2; ks++) {
                uint32_t bh[4][2], bl[4][2];
#pragma unroll
                for (int ni = 0; ni < 4; ni++) {
                    uint32_t off = (uint32_t)((wn * 32 + ni * 8 + (lane & 7)) * 80 + ks * 32 +
                                              ((lane >> 3) & 1) * 16);
                    ldm_x2(bh[ni], sb + bOffH + off);
                    ldm_x2(bl[ni], sb + bOffH + 10240 + off);
                }
#pragma unroll
                for (int mi = 0; mi < 4; mi++) {
                    uint32_t ah[4], al[4];
                    uint32_t off = (uint32_t)((wm * 64 + mi * 16 + (lane & 15)) * 80 + ks * 32 +
                                              (lane >> 4) * 16);
                    ldm_x4(ah, sb + SM_AH + off);
                    ldm_x4(al, sb + SM_AL + off);
#pragma unroll
                    for (int ni = 0; ni < 4; ni++) {
                        mma16816(acc[mi][ni], ah, bh[ni]);
                        mma16816(acc[mi][ni], ah, bl[ni]);
                        mma16816(acc[mi][ni], al, bh[ni]);
                    }
                }
            }
        }
        if (bMode == 2 && more) STOREB8((c + 1) & 1);
        __syncthreads();
    }
#undef ISSUE_A8
#undef ISSUE_B8
#undef LDGB8
#undef STOREB8

    const int trow = lane >> 2, tcol = (lane & 3) * 2;

    if constexpr (EPI == EPI_STORE) {
        __nv_bfloat16* Chi = g_act + offC + (long)b * sC;
        __nv_bfloat16* Clo = Chi + planeC;
#pragma unroll
        for (int mi = 0; mi < 4; mi++) {
            int r0 = m0 + wm * 64 + mi * 16 + trow;
#pragma unroll
            for (int ni = 0; ni < 4; ni++) {
                int c0 = n0 + wn * 32 + ni * 8 + tcol;
                if (c0 >= Nreal) continue;
                float v0 = acc[mi][ni][0], v1 = acc[mi][ni][1];
                float v2 = acc[mi][ni][2], v3 = acc[mi][ni][3];
                if (doRelu) {
                    v0 = fmaxf(v0, 0.f); v1 = fmaxf(v1, 0.f);
                    v2 = fmaxf(v2, 0.f); v3 = fmaxf(v3, 0.f);
                }
                __nv_bfloat162 h01, l01, h23, l23;
                split1(v0, h01.x, l01.x); split1(v1, h01.y, l01.y);
                split1(v2, h23.x, l23.x); split1(v3, h23.y, l23.y);
                long e0 = (long)r0 * ldc + c0, e1 = (long)(r0 + 8) * ldc + c0;
                *reinterpret_cast<__nv_bfloat162*>(Chi + e0) = h01;
                *reinterpret_cast<__nv_bfloat162*>(Clo + e0) = l01;
                *reinterpret_cast<__nv_bfloat162*>(Chi + e1) = h23;
                *reinterpret_cast<__nv_bfloat162*>(Clo + e1) = l23;
            }
        }
    } else {  // EPI_ATT / EPI_SIM
        float* smF = reinterpret_cast<float*>(smem);  // 128x129
        const float bias = (EPI == EPI_ATT) ? biasPtr[0] : 0.f;
        const float* mRow = g_scratch + OFF_MASK1 + (long)b * Sn;
        const float* mCol = g_scratch + OFF_MASK2 + (long)b * Sn;
        if (!skipWarp) {
#pragma unroll
            for (int mi = 0; mi < 4; mi++) {
                int r0 = wm * 64 + mi * 16 + trow;
#pragma unroll
                for (int ni = 0; ni < 4; ni++) {
                    int c0 = wn * 32 + ni * 8 + tcol;
                    float v0 = acc[mi][ni][0], v1 = acc[mi][ni][1];
                    float v2 = acc[mi][ni][2], v3 = acc[mi][ni][3];
                    if (EPI == EPI_ATT) {
                        v0 += (abs(r0 - c0) >= 10) ? bias : 0.f;
                        v1 += (abs(r0 - c0 - 1) >= 10) ? bias : 0.f;
                        v2 += (abs(r0 + 8 - c0) >= 10) ? bias : 0.f;
                        v3 += (abs(r0 + 8 - c0 - 1) >= 10) ? bias : 0.f;
                    } else {
                        float rm0 = mRow[r0], rm1 = mRow[r0 + 8];
                        float cm0 = mCol[c0], cm1 = mCol[c0 + 1];
                        v0 *= rm0 * cm0; v1 *= rm0 * cm1;
                        v2 *= rm1 * cm0; v3 *= rm1 * cm1;
                    }
                    smF[r0 * 129 + c0] = v0;
                    smF[r0 * 129 + c0 + 1] = v1;
                    smF[(r0 + 8) * 129 + c0] = v2;
                    smF[(r0 + 8) * 129 + c0 + 1] = v3;
                }
            }
        }
        __syncthreads();
        if (EPI == EPI_ATT && bSameA) {
            // mirror missing quadrant (rows 64-127 x cols 0-63) from transpose
            for (int idx = tid; idx < 64 * 64; idx += 256) {
                int r = 64 + (idx >> 6), c = idx & 63;
                smF[r * 129 + c] = smF[c * 129 + r];
            }
            __syncthreads();
        }
        {
            __nv_bfloat16* Chi = g_act + offC + (long)b * sC;
            __nv_bfloat16* Clo = Chi + planeC;
            for (int r = wid; r < 128; r += 8) {
                float v[4];
                float mx = -1e30f;
#pragma unroll
                for (int k = 0; k < 4; k++) {
                    v[k] = smF[r * 129 + lane + k * 32];
                    mx = fmaxf(mx, v[k]);
                }
#pragma unroll
                for (int o = 16; o; o >>= 1) mx = fmaxf(mx, __shfl_xor_sync(0xffffffffu, mx, o));
                float s = 0.f;
#pragma unroll
                for (int k = 0; k < 4; k++) {
                    v[k] = expf(v[k] - mx);
                    s += v[k];
                }
#pragma unroll
                for (int o = 16; o; o >>= 1) s += __shfl_xor_sync(0xffffffffu, s, o);
                float inv = 1.0f / s;
#pragma unroll
                for (int k = 0; k < 4; k++) {
                    __nv_bfloat16 h, l;
                    split1(v[k] * inv, h, l);
                    long e = (long)r * Sn + lane + k * 32;
                    Chi[e] = h;
                    Clo[e] = l;
                }
            }
        }
        if constexpr (EPI == EPI_SIM) {
            __nv_bfloat16* C2hi = g_act + offC2 + (long)b * sC;
            __nv_bfloat16* C2lo = C2hi + planeC2;
            for (int c = wid; c < 128; c += 8) {
                float v[4];
                float mx = -1e30f;
#pragma unroll
                for (int k = 0; k < 4; k++) {
                    v[k] = smF[(lane + k * 32) * 129 + c];
                    mx = fmaxf(mx, v[k]);
                }
#pragma unroll
                for (int o = 16; o; o >>= 1) mx = fmaxf(mx, __shfl_xor_sync(0xffffffffu, mx, o));
                float s = 0.f;
#pragma unroll
                for (int k = 0; k < 4; k++) {
                    v[k] = expf(v[k] - mx);
                    s += v[k];
                }
#pragma unroll
                for (int o = 16; o; o >>= 1) s += __shfl_xor_sync(0xffffffffu, s, o);
                float inv = 1.0f / s;
#pragma unroll
                for (int k = 0; k < 4; k++) {
                    __nv_bfloat16 h, l;
                    split1(v[k] * inv, h, l);
                    long e = (long)c * Sn + lane + k * 32;
                    C2hi[e] = h;
                    C2lo[e] = l;
                }
            }
        }
    }
}

// ===========================================================================
// k_gemm4 — 4-warp (128 thread) GEMM.  (R13/R14-proven, unchanged)
// WN=2: 2x2 warp grid, 64x64 warp tiles, CTA tile 128 cols.
// WN=1: 4x1 warp grid, CTA tile 64 cols (N-edge variant).
// A triple-buffered / B double-buffered cp.async pipeline, 80B rows.
// ===========================================================================
template <int EPI, int WN>
__global__ void __launch_bounds__(128, 2)
k_gemm4(long offA, int lda, long sA, long planeA,
        long offB, int ldb, long sB, long planeB,
        long offC, int ldc, long sC, long planeC,
        int n0base, int Nreal, int K, int doRelu) {
    constexpr int MI = (WN == 2) ? 4 : 2;
    constexpr int NT = WN * 64;
    constexpr int WMC = 4 / WN;
    extern __shared__ __align__(16) char smem[];
    const uint32_t sb0 = smem_u32(smem);
    const int tid = threadIdx.x;
    const int lane = tid & 31, wid = tid >> 5;
    const int wm = (WN == 2) ? (wid & 1) : wid;
    const int wn = (WN == 2) ? (wid >> 1) : 0;
    const int n0 = n0base + blockIdx.x * NT;
    const int m0 = blockIdx.y * 128;
    const int b = blockIdx.z;

    const __nv_bfloat16* Ahi = g_act + offA + (long)b * sA;
    const __nv_bfloat16* Alo = Ahi + planeA;
    const __nv_bfloat16* Bhi = g_wt + offB + (long)b * sB;
    const __nv_bfloat16* Blo = Bhi + planeB;

    float acc[MI][8][4] = {};
    const int crow = tid >> 2, cch = tid & 3;
    const int nChunks = (K + 31) >> 5;

#define ISSUE_A4(c, stg)                                                        \
    {                                                                           \
        const int k0 = (c) << 5;                                                \
        const int gk = k0 + cch * 8;                                            \
        int bytes = K - gk;                                                     \
        bytes = bytes < 0 ? 0 : (bytes > 8 ? 8 : bytes);                        \
        bytes *= 2;                                                             \
        _Pragma("unroll") for (int i = 0; i < 4; i++) {                         \
            int row = crow + i * 32;                                            \
            long ro = (long)(m0 + row) * lda;                                   \
            uint32_t d = sb0 + (stg)*S4_STG + (uint32_t)(row * 80 + cch * 16);  \
            cp16(d, Ahi + ro + (bytes ? gk : 0), bytes);                        \
            cp16(d + 10240, Alo + ro + (bytes ? gk : 0), bytes);                \
        }                                                                       \
    }
#define ISSUE_B4(c, stg)                                                        \
    {                                                                           \
        const int k0 = (c) << 5;                                                \
        const int gk = k0 + cch * 8;                                            \
        int kb = K - gk;                                                        \
        kb = kb < 0 ? 0 : (kb > 8 ? 8 : kb);                                    \
        kb *= 2;                                                                \
        _Pragma("unroll") for (int i = 0; i < NT / 32; i++) {                   \
            int n = crow + i * 32;                                              \
            int gn = n0 + n;                                                    \
            int bytes = (gn < Nreal) ? kb : 0;                                  \
            long ro = bytes ? (long)gn * ldb + gk : 0;                          \
            uint32_t d = sb0 + S4_B_BASE + (stg)*S4_STG +                       \
                         (uint32_t)(n * 80 + cch * 16);                         \
            cp16(d, Bhi + ro, bytes);                                           \
            cp16(d + 10240, Blo + ro, bytes);                                   \
        }                                                                       \
    }

    ISSUE_A4(0, 0);
    if (1 < nChunks) ISSUE_A4(1, 1);
    ISSUE_B4(0, 0);
    cp_commit();
    if (2 < nChunks) ISSUE_A4(2, 2);
    if (1 < nChunks) ISSUE_B4(1, 1);
    cp_commit();

    for (int c = 0; c < nChunks; c++) {
        cp_wait<1>();
        __syncthreads();

        const uint32_t sa = sb0 + (uint32_t)((c % 3) * S4_STG);
        const uint32_t sbb = sb0 + (uint32_t)(S4_B_BASE + (c & 1) * S4_STG);
#pragma unroll
        for (int ks = 0; ks < 2; ks++) {
            uint32_t bh[8][2], bl[8][2];
#pragma unroll
            for (int p = 0; p < 4; p++) {
                uint32_t row = (uint32_t)(wn * 64 + p * 16 + ((lane >> 4) << 3) + (lane & 7));
                uint32_t off = row * 80 + (uint32_t)(ks * 32 + ((lane >> 3) & 1) * 16);
                uint32_t r4[4];
                ldm_x4(r4, sbb + off);
                bh[2 * p][0] = r4[0]; bh[2 * p][1] = r4[1];
                bh[2 * p + 1][0] = r4[2]; bh[2 * p + 1][1] = r4[3];
                ldm_x4(r4, sbb + 10240 + off);
                bl[2 * p][0] = r4[0]; bl[2 * p][1] = r4[1];
                bl[2 * p + 1][0] = r4[2]; bl[2 * p + 1][1] = r4[3];
            }
#pragma unroll
            for (int mi = 0; mi < MI; mi++) {
                uint32_t ah[4], al[4];
                uint32_t off = (uint32_t)((wm * (MI * 16) + mi * 16 + (lane & 15)) * 80 +
                                          ks * 32 + (lane >> 4) * 16);
                ldm_x4(ah, sa + off);
                ldm_x4(al, sa + 10240 + off);
#pragma unroll
                for (int ni = 0; ni < 8; ni++) {
                    mma16816(acc[mi][ni], ah, bh[ni]);
                    mma16816(acc[mi][ni], ah, bl[ni]);
                    mma16816(acc[mi][ni], al, bh[ni]);
                }
            }
        }
        __syncthreads();
        if (c + 3 < nChunks) ISSUE_A4(c + 3, (c + 3) % 3);
        if (c + 2 < nChunks) ISSUE_B4(c + 2, (c + 2) & 1);
        cp_commit();
    }
#undef ISSUE_A4
#undef ISSUE_B4

    const int trow = lane >> 2, tcol = (lane & 3) * 2;

    if constexpr (EPI == EPI_STORE) {
        __nv_bfloat16* Chi = g_act + offC + (long)b * sC;
        __nv_bfloat16* Clo = Chi + planeC;
#pragma unroll
        for (int mi = 0; mi < MI; mi++) {
            int r0 = m0 + wm * (MI * 16) + mi * 16 + trow;
#pragma unroll
            for (int ni = 0; ni < 8; ni++) {
                int c0 = n0 + wn * 64 + ni * 8 + tcol;
                if (c0 >= Nreal) continue;
                float v0 = acc[mi][ni][0], v1 = acc[mi][ni][1];
                float v2 = acc[mi][ni][2], v3 = acc[mi][ni][3];
                if (doRelu) {
                    v0 = fmaxf(v0, 0.f); v1 = fmaxf(v1, 0.f);
                    v2 = fmaxf(v2, 0.f); v3 = fmaxf(v3, 0.f);
                }
                __nv_bfloat162 h01, l01, h23, l23;
                split1(v0, h01.x, l01.x); split1(v1, h01.y, l01.y);
                split1(v2, h23.x, l23.x); split1(v3, h23.y, l23.y);
                long e0 = (long)r0 * ldc + c0, e1 = (long)(r0 + 8) * ldc + c0;
                *reinterpret_cast<__nv_bfloat162*>(Chi + e0) = h01;
                *reinterpret_cast<__nv_bfloat162*>(Clo + e0) = l01;
                *reinterpret_cast<__nv_bfloat162*>(Chi + e1) = h23;
                *reinterpret_cast<__nv_bfloat162*>(Clo + e1) = l23;
            }
        }
    } else {  // EPI_POOL
        const int side = blockIdx.z;
        const float* mask = g_scratch + (side ? OFF_MASK2 : OFF_MASK1) + (long)blockIdx.y * Sn;
        float* smP = reinterpret_cast<float*>(smem);  // [WMC][NT]
        float p[8][2];
#pragma unroll
        for (int ni = 0; ni < 8; ni++) { p[ni][0] = 0.f; p[ni][1] = 0.f; }
#pragma unroll
        for (int mi = 0; mi < MI; mi++) {
            int r0 = wm * (MI * 16) + mi * 16 + trow;
            float m0v = mask[r0], m1v = mask[r0 + 8];
#pragma unroll
            for (int ni = 0; ni < 8; ni++) {
                p[ni][0] += fmaxf(acc[mi][ni][0], 0.f) * m0v + fmaxf(acc[mi][ni][2], 0.f) * m1v;
                p[ni][1] += fmaxf(acc[mi][ni][1], 0.f) * m0v + fmaxf(acc[mi][ni][3], 0.f) * m1v;
            }
        }
#pragma unroll
        for (int ni = 0; ni < 8; ni++) {
#pragma unroll
            for (int o = 4; o <= 16; o <<= 1) {
                p[ni][0] += __shfl_xor_sync(0xffffffffu, p[ni][0], o);
                p[ni][1] += __shfl_xor_sync(0xffffffffu, p[ni][1], o);
            }
        }
        __syncthreads();
        if (lane < 4) {
#pragma unroll
            for (int ni = 0; ni < 8; ni++) {
                smP[wm * NT + wn * 64 + ni * 8 + lane * 2] = p[ni][0];
                smP[wm * NT + wn * 64 + ni * 8 + lane * 2 + 1] = p[ni][1];
            }
        }
        __syncthreads();
        if (tid < NT) {
            int gcol = n0 + tid;
            if (gcol < Nreal) {
                float s = 0.f;
#pragma unroll
                for (int w = 0; w < WMC; w++) s += smP[w * NT + tid];
                g_scratch[OFF_POOL + (long)blockIdx.y * 800 + (long)side * 400 + gcol] = s;
            }
        }
    }
}

// ---------------------------------------------------------------------------
// All weights: transpose + split, one launch. W [K][N] f32 -> [N][Kp] hi/lo
// ---------------------------------------------------------------------------
__global__ void k_wsplit_all(const float* __restrict__ w_intra,
                             const float* __restrict__ w_proj1,
                             const float* __restrict__ w_proj2,
                             const float* __restrict__ w_att,
                             const float* __restrict__ w_cmp1,
                             const float* __restrict__ w_cmp2) {
    const float* W;
    int K, N, Kp;
    long off;
    switch (blockIdx.y) {
        case 0: W = w_intra; K = En;     N = En;     Kp = EP;     off = WT_INTRA; break;
        case 1: W = w_proj1; K = 2 * En; N = Pn;     Kp = 2 * En; off = WT_PROJ1; break;
        case 2: W = w_proj2; K = 2 * En; N = Pn;     Kp = 2 * En; off = WT_PROJ2; break;
        case 3: W = w_att;   K = Pn;     N = Pn;     Kp = Pn;     off = WT_ATT;   break;
        case 4: W = w_cmp1;  K = 2 * Pn; N = 2 * Pn; Kp = 2 * Pn; off = WT_CMP1;  break;
        default: W = w_cmp2; K = 2 * Pn; N = 2 * Pn; Kp = 2 * Pn; off = WT_CMP2;  break;
    }
    long total = (long)K * N;
    long plane = (long)N * Kp;
    for (long i = (long)blockIdx.x * blockDim.x + threadIdx.x; i < total;
         i += (long)gridDim.x * blockDim.x) {
        int n = (int)(i / K), k = (int)(i % K);
        float v = W[(long)k * N + n];
        __nv_bfloat16 h, l;
        split1(v, h, l);
        g_wt[off + (long)n * Kp + k] = h;
        g_wt[off + plane + (long)n * Kp + k] = l;
    }
}

// ---------------------------------------------------------------------------
// Non-GEMM kernels
// ---------------------------------------------------------------------------
__global__ void k_seqmask(const int* __restrict__ x1, const int* __restrict__ x2) {
    int b = blockIdx.x;
    const int* x = blockIdx.y ? x2 : x1;
    float* m = g_scratch + (blockIdx.y ? OFF_MASK2 : OFF_MASK1);
    int t = threadIdx.x;
    int nz = __syncthreads_count(x[b * Sn + t] != 0);
    m[b * Sn + t] = (t < nz) ? 1.0f : 0.0f;
}

__global__ void k_gather(const int* __restrict__ x1, const int* __restrict__ x2,
                         const float* __restrict__ emb) {
    int side = blockIdx.y;
    const int* x = side ? x2 : x1;
    int lane = threadIdx.x & 31;
    long bs = (long)blockIdx.x * 8 + (threadIdx.x >> 5);
    int row = x[bs];
    const float* e = emb + (long)row * En;
    float v[10];
    float ss = 0.f;
#pragma unroll
    for (int i = 0; i < 10; i++) {
        int idx = lane + i * 32;
        v[i] = (idx < En) ? e[idx] : 0.f;
        ss += v[i] * v[i];
    }
#pragma unroll
    for (int o = 16; o; o >>= 1) ss += __shfl_xor_sync(0xffffffffu, ss, o);
    float inv = 1.0f / sqrtf(fmaxf(ss, 1e-12f));
    __nv_bfloat16* hi = g_act + ACT_CAT + (long)side * BS * 600 + bs * 600;
    __nv_bfloat16* lo = hi + CAT_PL;
#pragma unroll
    for (int i = 0; i < 10; i++) {
        int idx = lane + i * 32;
        if (idx < En) {
            __nv_bfloat16 h, l;
            split1(v[i] * inv, h, l);
            hi[idx] = h;
            lo[idx] = l;
        }
    }
}

__global__ void k_final(const float* __restrict__ w_agg, float* __restrict__ out) {
    int b = blockIdx.x;
    int tid = threadIdx.x;
    int c = tid >> 5, lane = tid & 31;
    const float* p = g_scratch + OFF_POOL + (long)b * 800;
    float acc = 0.f;
    for (int n = lane; n < 800; n += 32) acc += p[n] * w_agg[n * Cn + c];
#pragma unroll
    for (int o = 16; o; o >>= 1) acc += __shfl_xor_sync(0xffffffffu, acc, o);
    if (lane == 0) out[b * Cn + c] = fmaxf(acc, 0.f);
}

// ---------------------------------------------------------------------------
// Orchestration
// ---------------------------------------------------------------------------
extern "C" void kernel_launch(void* const* d_in, const int* in_sizes, int n_in,
                              void* d_out, int out_size) {
    const int* x1 = (const int*)d_in[0];
    const int* x2 = (const int*)d_in[1];
    const float* emb = (const float*)d_in[2];
    const float* w_intra = (const float*)d_in[3];
    const float* bias_intra = (const float*)d_in[4];
    const float* w_proj1 = (const float*)d_in[5];
    const float* w_proj2 = (const float*)d_in[6];
    const float* w_att = (const float*)d_in[7];
    const float* w_cmp1 = (const float*)d_in[8];
    const float* w_cmp2 = (const float*)d_in[9];
    const float* w_agg = (const float*)d_in[10];
    float* out = (float*)d_out;

    cudaFuncSetAttribute(k_gemm8<EPI_STORE>, cudaFuncAttributeMaxDynamicSharedMemorySize, SMEM8_BYTES);
    cudaFuncSetAttribute(k_gemm8<EPI_ATT>, cudaFuncAttributeMaxDynamicSharedMemorySize, SMEM8_BYTES);
    cudaFuncSetAttribute(k_gemm8<EPI_SIM>, cudaFuncAttributeMaxDynamicSharedMemorySize, SMEM8_BYTES);
    cudaFuncSetAttribute((const void*)k_gemm4<EPI_STORE, 2>, cudaFuncAttributeMaxDynamicSharedMemorySize, SMEM4_BYTES);
    cudaFuncSetAttribute((const void*)k_gemm4<EPI_STORE, 1>, cudaFuncAttributeMaxDynamicSharedMemorySize, SMEM4_BYTES);
    cudaFuncSetAttribute((const void*)k_gemm4<EPI_POOL, 2>, cudaFuncAttributeMaxDynamicSharedMemorySize, SMEM4_BYTES);
    cudaFuncSetAttribute((const void*)k_gemm4<EPI_POOL, 1>, cudaFuncAttributeMaxDynamicSharedMemorySize, SMEM4_BYTES);

    k_seqmask<<<dim3(Bn, 2), Sn>>>(x1, x2);
    k_gather<<<dim3((unsigned)(BS / 8), 2), 256>>>(x1, x2, emb);
    k_wsplit_all<<<dim3(160, 6), 256>>>(w_intra, w_proj1, w_proj2, w_att, w_cmp1, w_cmp2);

    // f = relu(e @ w_intra): bulk 2 full tiles + 64-wide edge (N=300)
    k_gemm4<EPI_STORE, 2><<<dim3(2, 256, 2), 128, SMEM4_BYTES>>>(
        ACT_CAT, 600, BS * 600, CAT_PL,
        WT_INTRA, EP, 0, 300L * EP,
        ACT_F, EP, BS * EP, F_PL,
        0, En, En, 1);
    k_gemm4<EPI_STORE, 1><<<dim3(1, 256, 2), 128, SMEM4_BYTES>>>(
        ACT_CAT, 600, BS * 600, CAT_PL,
        WT_INTRA, EP, 0, 300L * EP,
        ACT_F, EP, BS * EP, F_PL,
        256, En, En, 1);

    // att = softmax_rows(f@f^T + dbias): symmetric, parity-balanced skip
    k_gemm8<EPI_ATT><<<dim3(1, 1, 2 * Bn), 256, SMEM8_BYTES>>>(
        ACT_F, EP, (long)Sn * EP, F_PL,
        1, ACT_F, EP, (long)Sn * EP, F_PL,
        ACT_ATT, Sn, (long)Sn * Sn, ATT_PL, 0, 0,
        NO_SPLIT, 0, 0, 0,
        Sn, En, 0, bias_intra, 1);

    // xp[g] = att[g] @ e[g]: B N-major -> cat cols 300:600
    k_gemm8<EPI_STORE><<<dim3(3, 1, 2 * Bn), 256, SMEM8_BYTES>>>(
        ACT_ATT, Sn, (long)Sn * Sn, ATT_PL,
        2, ACT_CAT, 600, (long)Sn * 600, CAT_PL,
        ACT_CAT + En, 600, (long)Sn * 600, CAT_PL, 0, 0,
        NO_SPLIT, 0, 0, 0,
        En, Sn, 0, nullptr, 0);

    // x_proj = relu(cat @ w_proj{1,2}): [2 x BS x 200], K=600
    k_gemm4<EPI_STORE, 2><<<dim3(2, 256, 2), 128, SMEM4_BYTES>>>(
        ACT_CAT, 600, BS * 600, CAT_PL,
        WT_PROJ1, 600, WT_PROJ2 - WT_PROJ1, 120000,
        ACT_CATP, 400, BS * 400, CATP_PL,
        0, Pn, 2 * En, 1);

    // fa = relu(x_proj @ w_att): [2 x BS x 200], K=200
    k_gemm4<EPI_STORE, 2><<<dim3(2, 256, 2), 128, SMEM4_BYTES>>>(
        ACT_CATP, 400, BS * 400, CATP_PL,
        WT_ATT, Pn, 0, 40000,
        ACT_FA, Pn, BS * Pn, FA_PL,
        0, Pn, Pn, 1);

    // sim: fused mask + row softmax (-> SIM) + col softmax^T (-> SMT)
    k_gemm8<EPI_SIM><<<dim3(1, 1, Bn), 256, SMEM8_BYTES>>>(
        ACT_FA, Pn, (long)Sn * Pn, FA_PL,
        1, ACT_FA + BS * Pn, Pn, (long)Sn * Pn, FA_PL,
        ACT_SIM, Sn, (long)Sn * Sn, SIM_PL,
        ACT_SMT, SMT_PL,
        NO_SPLIT, 0, 0, 0,
        Sn, Pn, 0, nullptr, 0);

    // beta (z<256) and alpha (z>=256) merged
    k_gemm8<EPI_STORE><<<dim3(2, 1, 2 * Bn), 256, SMEM8_BYTES>>>(
        ACT_SIM, Sn, (long)Sn * Sn, SIM_PL,
        2, ACT_CATP + BS * 400, 400, (long)Sn * 400, CATP_PL,
        ACT_CATP + Pn, 400, (long)Sn * 400, CATP_PL, 0, 0,
        Bn, ACT_SMT, ACT_CATP, ACT_CATP + BS * 400 + Pn,
        Pn, Sn, 0, nullptr, 0);

    // v = relu([xp|attend] @ w_cmp{1,2}) + pooling: bulk 3 tiles + 64-wide edge
    k_gemm4<EPI_POOL, 2><<<dim3(3, 256, 2), 128, SMEM4_BYTES>>>(
        ACT_CATP, 400, BS * 400, CATP_PL,
        WT_CMP1, 2 * Pn, WT_CMP2 - WT_CMP1, 160000,
        0, 0, 0, 0,
        0, 2 * Pn, 2 * Pn, 1);
    k_gemm4<EPI_POOL, 1><<<dim3(1, 256, 2), 128, SMEM4_BYTES>>>(
        ACT_CATP, 400, BS * 400, CATP_PL,
        WT_CMP1, 2 * Pn, WT_CMP2 - WT_CMP1, 160000,
        0, 0, 0, 0,
        384, 2 * Pn, 2 * Pn, 1);

    k_final<<<Bn, 96>>>(w_agg, out);
}

// round 17
// speedup vs baseline: 1.0271x; 1.0153x over previous
#include <cuda_runtime.h>
#include <cuda_bf16.h>
#include <math.h>
#include <stdint.h>

// ---------------------------------------------------------------------------
// Problem constants
// ---------------------------------------------------------------------------
namespace {
constexpr int Bn = 256, Sn = 128, En = 300, Pn = 200, Cn = 3;
constexpr long BS = (long)Bn * Sn;  // 32768
constexpr int EP = 304;             // 300 padded to 16B multiple

// ---- f32 scratch (masks + pool)
constexpr long OFF_MASK1 = 0;
constexpr long OFF_MASK2 = OFF_MASK1 + BS;
constexpr long OFF_POOL  = OFF_MASK2 + BS;
constexpr long F32_TOTAL = OFF_POOL + (long)Bn * 4 * Pn;

// ---- bf16 activation arena: every tensor is two planes (hi, lo = +PLANE)
constexpr long ACT_CAT  = 0;                        // [2][BS][600]
constexpr long CAT_PL   = 2 * BS * 600;
constexpr long ACT_F    = ACT_CAT + 2 * CAT_PL;     // [2*BS][304]
constexpr long F_PL     = 2 * BS * EP;
constexpr long ACT_ATT  = ACT_F + 2 * F_PL;         // [2*B][S][S] (softmaxed)
constexpr long ATT_PL   = 2 * BS * Sn;
constexpr long ACT_CATP = ACT_ATT + 2 * ATT_PL;     // [2][BS][400]
constexpr long CATP_PL  = 2 * BS * 2 * Pn;
constexpr long ACT_FA   = ACT_CATP + 2 * CATP_PL;   // [2][BS][200]
constexpr long FA_PL    = 2 * BS * Pn;
constexpr long ACT_SIM  = ACT_FA + 2 * FA_PL;       // [B][S][S] row-softmaxed
constexpr long SIM_PL   = BS * Sn;
constexpr long ACT_SMT  = ACT_SIM + 2 * SIM_PL;     // [B][S][S] col-softmax^T
constexpr long SMT_PL   = BS * Sn;
constexpr long ACT_TOTAL = ACT_SMT + 2 * SMT_PL;

// ---- split weights, bf16 [N][Kpad]; lo plane at +N*Kpad
constexpr long WT_INTRA = 0;                          // 300 x 304
constexpr long WT_PROJ1 = WT_INTRA + 2L * 300 * EP;   // 200 x 600
constexpr long WT_PROJ2 = WT_PROJ1 + 2L * 120000;
constexpr long WT_ATT   = WT_PROJ2 + 2L * 120000;     // 200 x 200
constexpr long WT_CMP1  = WT_ATT + 2L * 40000;        // 400 x 400
constexpr long WT_CMP2  = WT_CMP1 + 2L * 160000;
constexpr long WT_TOTAL = WT_CMP2 + 2L * 160000;

// ---- k_gemm8 staging smem (80B rows, 2 buffers)
constexpr int SM_AH = 0;
constexpr int SM_AL = 10240;
constexpr int SM_BH = 20480;
constexpr int SM_BL = 30720;
constexpr int SM_BUF = 40960;
constexpr int SMEM8_BYTES = 2 * SM_BUF;  // 80 KB (also covers 128x129 f32)

// ---- k_gemm4 staging: 80B rows; A triple-buffered, B double-buffered
constexpr int S4_STG    = 20480;
constexpr int S4_B_BASE = 61440;
constexpr int SMEM4_BYTES = 102400;  // 100 KB -> 2 CTAs/SM

enum { EPI_STORE = 0, EPI_ATT = 1, EPI_SIM = 2, EPI_POOL = 3 };
constexpr int NO_SPLIT = 1 << 30;
}  // namespace

__device__ float g_scratch[F32_TOTAL];
__device__ __nv_bfloat16 g_act[ACT_TOTAL];
__device__ __nv_bfloat16 g_wt[WT_TOTAL];

// ---------------------------------------------------------------------------
// helpers
// ---------------------------------------------------------------------------
__device__ __forceinline__ uint32_t smem_u32(const void* p) {
    uint32_t a;
    asm("{ .reg .u64 t; cvta.to.shared.u64 t, %1; cvt.u32.u64 %0, t; }" : "=r"(a) : "l"(p));
    return a;
}
__device__ __forceinline__ void split1(float v, __nv_bfloat16& h, __nv_bfloat16& l) {
    h = __float2bfloat16(v);
    l = __float2bfloat16(v - __bfloat162float(h));
}
__device__ __forceinline__ void cp16(uint32_t dst, const void* src, int bytes) {
    asm volatile("cp.async.cg.shared.global [%0], [%1], 16, %2;"
                 :: "r"(dst), "l"(src), "r"(bytes) : "memory");
}
__device__ __forceinline__ void cp_commit() {
    asm volatile("cp.async.commit_group;" ::: "memory");
}
template <int N>
__device__ __forceinline__ void cp_wait() {
    asm volatile("cp.async.wait_group %0;" :: "n"(N) : "memory");
}
__device__ __forceinline__ void ldm_x4(uint32_t* r, uint32_t addr) {
    asm volatile("ldmatrix.sync.aligned.m8n8.x4.shared.b16 {%0,%1,%2,%3}, [%4];"
                 : "=r"(r[0]), "=r"(r[1]), "=r"(r[2]), "=r"(r[3]) : "r"(addr));
}
__device__ __forceinline__ void ldm_x2(uint32_t* r, uint32_t addr) {
    asm volatile("ldmatrix.sync.aligned.m8n8.x2.shared.b16 {%0,%1}, [%2];"
                 : "=r"(r[0]), "=r"(r[1]) : "r"(addr));
}
__device__ __forceinline__ void mma16816(float* c, const uint32_t* a, const uint32_t* b) {
    asm volatile(
        "mma.sync.aligned.m16n8k16.row.col.f32.bf16.bf16.f32 "
        "{%0,%1,%2,%3}, {%4,%5,%6,%7}, {%8,%9}, {%0,%1,%2,%3};"
        : "+f"(c[0]), "+f"(c[1]), "+f"(c[2]), "+f"(c[3])
        : "r"(a[0]), "r"(a[1]), "r"(a[2]), "r"(a[3]), "r"(b[0]), "r"(b[1]));
}

// ===========================================================================
// k_gemm8 — 8-warp (256 thread) GEMM, 2x4 warp grid, 64x32 warp tiles.
// bSameA: B tile is identical to A tile (f@f^T) -> stage once, read B frags
// from the A smem region.
// ===========================================================================
template <int EPI>
__global__ void __launch_bounds__(256, 2)
k_gemm8(long offA, int lda, long sA, long planeA,
        int bMode, long offB, int ldb, long sB, long planeB,
        long offC, int ldc, long sC, long planeC,
        long offC2, long planeC2,
        int altSplit, long offAa, long offBa, long offCa,
        int Nreal, int K, int doRelu, const float* biasPtr, int bSameA) {
    extern __shared__ __align__(16) char smem[];
    const uint32_t sb0 = smem_u32(smem);
    const int tid = threadIdx.x;
    const int lane = tid & 31, wid = tid >> 5;
    const int wm = wid & 1, wn = wid >> 1;  // 2x4 warp grid -> 64x32 per warp
    const int n0 = blockIdx.x * 128, m0 = blockIdx.y * 128;
    int b = blockIdx.z;
    if (b >= altSplit) {
        b -= altSplit;
        offA = offAa; offB = offBa; offC = offCa;
    }

    const __nv_bfloat16* Ahi = g_act + offA + (long)b * sA;
    const __nv_bfloat16* Alo = Ahi + planeA;
    const __nv_bfloat16* Bhi = g_act + offB + (long)b * sB;
    const __nv_bfloat16* Blo = Bhi + planeB;

    float acc[4][4][4] = {};
    const int crow = tid >> 2, cch = tid & 3;
    const int nN = (tid & 63) * 2, nKb = tid >> 6;
    const int nChunks = (K + 31) >> 5;
    const uint32_t bOffH = bSameA ? (uint32_t)SM_AH : (uint32_t)SM_BH;
    uint32_t pfh[8], pfl[8];

#define ISSUE_A8(c, bi)                                                         \
    {                                                                           \
        const int k0 = (c) << 5;                                                \
        _Pragma("unroll") for (int i = 0; i < 2; i++) {                         \
            int row = crow + i * 64;                                            \
            int gk = k0 + cch * 8;                                              \
            int bytes = K - gk;                                                 \
            bytes = bytes < 0 ? 0 : (bytes > 8 ? 8 : bytes);                    \
            bytes *= 2;                                                         \
            long ro = (long)(m0 + row) * lda;                                   \
            uint32_t d = sb0 + (bi)*SM_BUF + (uint32_t)(row * 80 + cch * 16);   \
            cp16(d + SM_AH, Ahi + ro + (bytes ? gk : 0), bytes);                \
            cp16(d + SM_AL, Alo + ro + (bytes ? gk : 0), bytes);                \
        }                                                                       \
    }
#define ISSUE_B8(c, bi)                                                         \
    {                                                                           \
        const int k0 = (c) << 5;                                                \
        _Pragma("unroll") for (int i = 0; i < 2; i++) {                         \
            int n = crow + i * 64;                                              \
            int gn = n0 + n;                                                    \
            int gk = k0 + cch * 8;                                              \
            int bytes = K - gk;                                                 \
            bytes = bytes < 0 ? 0 : (bytes > 8 ? 8 : bytes);                    \
            bytes *= 2;                                                         \
            if (gn >= Nreal) bytes = 0;                                         \
            long ro = bytes ? (long)gn * ldb + gk : 0;                          \
            uint32_t d = sb0 + (bi)*SM_BUF + (uint32_t)(n * 80 + cch * 16);     \
            cp16(d + SM_BH, Bhi + ro, bytes);                                   \
            cp16(d + SM_BL, Blo + ro, bytes);                                   \
        }                                                                       \
    }
#define LDGB8(c)                                                                \
    {                                                                           \
        const int k0 = (c) << 5;                                                \
        const int gn = n0 + nN;                                                 \
        const bool nin = (gn < Nreal);                                          \
        _Pragma("unroll") for (int it = 0; it < 8; it++) {                      \
            int gk = k0 + nKb + it * 4;                                         \
            if (nin && gk < K) {                                                \
                long e = (long)gk * ldb + gn;                                   \
                pfh[it] = *reinterpret_cast<const uint32_t*>(Bhi + e);          \
                pfl[it] = *reinterpret_cast<const uint32_t*>(Blo + e);          \
            } else {                                                            \
                pfh[it] = 0; pfl[it] = 0;                                       \
            }                                                                   \
        }                                                                       \
    }
#define STOREB8(bi)                                                             \
    {                                                                           \
        char* sm = smem + (bi)*SM_BUF;                                          \
        _Pragma("unroll") for (int it = 0; it < 8; it++) {                      \
            int kk = nKb + it * 4;                                              \
            __nv_bfloat162 h2 = *reinterpret_cast<__nv_bfloat162*>(&pfh[it]);   \
            __nv_bfloat162 l2 = *reinterpret_cast<__nv_bfloat162*>(&pfl[it]);   \
            *reinterpret_cast<__nv_bfloat16*>(sm + SM_BH + nN * 80 + kk * 2) = h2.x; \
            *reinterpret_cast<__nv_bfloat16*>(sm + SM_BL + nN * 80 + kk * 2) = l2.x; \
            *reinterpret_cast<__nv_bfloat16*>(sm + SM_BH + (nN + 1) * 80 + kk * 2) = h2.y; \
            *reinterpret_cast<__nv_bfloat16*>(sm + SM_BL + (nN + 1) * 80 + kk * 2) = l2.y; \
        }                                                                       \
    }

    ISSUE_A8(0, 0);
    if (bMode < 2 && !bSameA) { ISSUE_B8(0, 0); }
    cp_commit();
    if (bMode == 2) { LDGB8(0); STOREB8(0); }

    for (int c = 0; c < nChunks; c++) {
        const bool more = (c + 1 < nChunks);
        if (more) {
            ISSUE_A8(c + 1, (c + 1) & 1);
            if (bMode < 2 && !bSameA) ISSUE_B8(c + 1, (c + 1) & 1);
            cp_commit();
            if (bMode == 2) LDGB8(c + 1);
        }
        if (more) cp_wait<1>(); else cp_wait<0>();
        __syncthreads();

        const uint32_t sb = sb0 + (uint32_t)((c & 1) * SM_BUF);
#pragma unroll
        for (int ks = 0; ks < 2; ks++) {
            uint32_t bh[4][2], bl[4][2];
#pragma unroll
            for (int ni = 0; ni < 4; ni++) {
                uint32_t off = (uint32_t)((wn * 32 + ni * 8 + (lane & 7)) * 80 + ks * 32 +
                                          ((lane >> 3) & 1) * 16);
                ldm_x2(bh[ni], sb + bOffH + off);
                ldm_x2(bl[ni], sb + bOffH + 10240 + off);
            }
#pragma unroll
            for (int mi = 0; mi < 4; mi++) {
                uint32_t ah[4], al[4];
                uint32_t off = (uint32_t)((wm * 64 + mi * 16 + (lane & 15)) * 80 + ks * 32 +
                                          (lane >> 4) * 16);
                ldm_x4(ah, sb + SM_AH + off);
                ldm_x4(al, sb + SM_AL + off);
#pragma unroll
                for (int ni = 0; ni < 4; ni++) {
                    mma16816(acc[mi][ni], ah, bh[ni]);
                    mma16816(acc[mi][ni], ah, bl[ni]);
                    mma16816(acc[mi][ni], al, bh[ni]);
                }
            }
        }
        if (bMode == 2 && more) STOREB8((c + 1) & 1);
        __syncthreads();
    }
#undef ISSUE_A8
#undef ISSUE_B8
#undef LDGB8
#undef STOREB8

    const int trow = lane >> 2, tcol = (lane & 3) * 2;

    if constexpr (EPI == EPI_STORE) {
        __nv_bfloat16* Chi = g_act + offC + (long)b * sC;
        __nv_bfloat16* Clo = Chi + planeC;
#pragma unroll
        for (int mi = 0; mi < 4; mi++) {
            int r0 = m0 + wm * 64 + mi * 16 + trow;
#pragma unroll
            for (int ni = 0; ni < 4; ni++) {
                int c0 = n0 + wn * 32 + ni * 8 + tcol;
                if (c0 >= Nreal) continue;
                float v0 = acc[mi][ni][0], v1 = acc[mi][ni][1];
                float v2 = acc[mi][ni][2], v3 = acc[mi][ni][3];
                if (doRelu) {
                    v0 = fmaxf(v0, 0.f); v1 = fmaxf(v1, 0.f);
                    v2 = fmaxf(v2, 0.f); v3 = fmaxf(v3, 0.f);
                }
                __nv_bfloat162 h01, l01, h23, l23;
                split1(v0, h01.x, l01.x); split1(v1, h01.y, l01.y);
                split1(v2, h23.x, l23.x); split1(v3, h23.y, l23.y);
                long e0 = (long)r0 * ldc + c0, e1 = (long)(r0 + 8) * ldc + c0;
                *reinterpret_cast<__nv_bfloat162*>(Chi + e0) = h01;
                *reinterpret_cast<__nv_bfloat162*>(Clo + e0) = l01;
                *reinterpret_cast<__nv_bfloat162*>(Chi + e1) = h23;
                *reinterpret_cast<__nv_bfloat162*>(Clo + e1) = l23;
            }
        }
    } else {  // EPI_ATT / EPI_SIM
        float* smF = reinterpret_cast<float*>(smem);  // 128x129
        const float bias = (EPI == EPI_ATT) ? biasPtr[0] : 0.f;
        const float* mRow = g_scratch + OFF_MASK1 + (long)b * Sn;
        const float* mCol = g_scratch + OFF_MASK2 + (long)b * Sn;
#pragma unroll
        for (int mi = 0; mi < 4; mi++) {
            int r0 = wm * 64 + mi * 16 + trow;
#pragma unroll
            for (int ni = 0; ni < 4; ni++) {
                int c0 = wn * 32 + ni * 8 + tcol;
                float v0 = acc[mi][ni][0], v1 = acc[mi][ni][1];
                float v2 = acc[mi][ni][2], v3 = acc[mi][ni][3];
                if (EPI == EPI_ATT) {
                    v0 += (abs(r0 - c0) >= 10) ? bias : 0.f;
                    v1 += (abs(r0 - c0 - 1) >= 10) ? bias : 0.f;
                    v2 += (abs(r0 + 8 - c0) >= 10) ? bias : 0.f;
                    v3 += (abs(r0 + 8 - c0 - 1) >= 10) ? bias : 0.f;
                } else {
                    float rm0 = mRow[r0], rm1 = mRow[r0 + 8];
                    float cm0 = mCol[c0], cm1 = mCol[c0 + 1];
                    v0 *= rm0 * cm0; v1 *= rm0 * cm1;
                    v2 *= rm1 * cm0; v3 *= rm1 * cm1;
                }
                smF[r0 * 129 + c0] = v0;
                smF[r0 * 129 + c0 + 1] = v1;
                smF[(r0 + 8) * 129 + c0] = v2;
                smF[(r0 + 8) * 129 + c0 + 1] = v3;
            }
        }
        __syncthreads();
        {
            __nv_bfloat16* Chi = g_act + offC + (long)b * sC;
            __nv_bfloat16* Clo = Chi + planeC;
            for (int r = wid; r < 128; r += 8) {
                float v[4];
                float mx = -1e30f;
#pragma unroll
                for (int k = 0; k < 4; k++) {
                    v[k] = smF[r * 129 + lane + k * 32];
                    mx = fmaxf(mx, v[k]);
                }
#pragma unroll
                for (int o = 16; o; o >>= 1) mx = fmaxf(mx, __shfl_xor_sync(0xffffffffu, mx, o));
                float s = 0.f;
#pragma unroll
                for (int k = 0; k < 4; k++) {
                    v[k] = expf(v[k] - mx);
                    s += v[k];
                }
#pragma unroll
                for (int o = 16; o; o >>= 1) s += __shfl_xor_sync(0xffffffffu, s, o);
                float inv = 1.0f / s;
#pragma unroll
                for (int k = 0; k < 4; k++) {
                    __nv_bfloat16 h, l;
                    split1(v[k] * inv, h, l);
                    long e = (long)r * Sn + lane + k * 32;
                    Chi[e] = h;
                    Clo[e] = l;
                }
            }
        }
        if constexpr (EPI == EPI_SIM) {
            __nv_bfloat16* C2hi = g_act + offC2 + (long)b * sC;
            __nv_bfloat16* C2lo = C2hi + planeC2;
            for (int c = wid; c < 128; c += 8) {
                float v[4];
                float mx = -1e30f;
#pragma unroll
                for (int k = 0; k < 4; k++) {
                    v[k] = smF[(lane + k * 32) * 129 + c];
                    mx = fmaxf(mx, v[k]);
                }
#pragma unroll
                for (int o = 16; o; o >>= 1) mx = fmaxf(mx, __shfl_xor_sync(0xffffffffu, mx, o));
                float s = 0.f;
#pragma unroll
                for (int k = 0; k < 4; k++) {
                    v[k] = expf(v[k] - mx);
                    s += v[k];
                }
#pragma unroll
                for (int o = 16; o; o >>= 1) s += __shfl_xor_sync(0xffffffffu, s, o);
                float inv = 1.0f / s;
#pragma unroll
                for (int k = 0; k < 4; k++) {
                    __nv_bfloat16 h, l;
                    split1(v[k] * inv, h, l);
                    long e = (long)c * Sn + lane + k * 32;
                    C2hi[e] = h;
                    C2lo[e] = l;
                }
            }
        }
    }
}

// ===========================================================================
// k_gemm4 — 4-warp (128 thread) GEMM.
// WN=2: 2x2 warp grid, 64x64 warp tiles, CTA tile 128 cols.
// WN=1: 4x1 warp grid (warps stacked in M, 32 rows each), CTA tile 64 cols
//       (compile-time narrow variant for N-edge tiles).
// A triple-buffered / B double-buffered cp.async pipeline, 80B rows.
// ===========================================================================
template <int EPI, int WN>
__global__ void __launch_bounds__(128, 2)
k_gemm4(long offA, int lda, long sA, long planeA,
        long offB, int ldb, long sB, long planeB,
        long offC, int ldc, long sC, long planeC,
        int n0base, int Nreal, int K, int doRelu) {
    constexpr int MI = (WN == 2) ? 4 : 2;   // 16-row m-tiles per warp
    constexpr int NT = WN * 64;             // CTA n-tile width
    constexpr int WMC = 4 / WN;             // warps stacked in M
    extern __shared__ __align__(16) char smem[];
    const uint32_t sb0 = smem_u32(smem);
    const int tid = threadIdx.x;
    const int lane = tid & 31, wid = tid >> 5;
    const int wm = (WN == 2) ? (wid & 1) : wid;
    const int wn = (WN == 2) ? (wid >> 1) : 0;
    const int n0 = n0base + blockIdx.x * NT;
    const int m0 = blockIdx.y * 128;
    const int b = blockIdx.z;

    const __nv_bfloat16* Ahi = g_act + offA + (long)b * sA;
    const __nv_bfloat16* Alo = Ahi + planeA;
    const __nv_bfloat16* Bhi = g_wt + offB + (long)b * sB;
    const __nv_bfloat16* Blo = Bhi + planeB;

    float acc[MI][8][4] = {};
    const int crow = tid >> 2, cch = tid & 3;  // staging: 32 rows/pass
    const int nChunks = (K + 31) >> 5;

#define ISSUE_A4(c, stg)                                                        \
    {                                                                           \
        const int k0 = (c) << 5;                                                \
        const int gk = k0 + cch * 8;                                            \
        int bytes = K - gk;                                                     \
        bytes = bytes < 0 ? 0 : (bytes > 8 ? 8 : bytes);                        \
        bytes *= 2;                                                             \
        _Pragma("unroll") for (int i = 0; i < 4; i++) {                         \
            int row = crow + i * 32;                                            \
            long ro = (long)(m0 + row) * lda;                                   \
            uint32_t d = sb0 + (stg)*S4_STG + (uint32_t)(row * 80 + cch * 16);  \
            cp16(d, Ahi + ro + (bytes ? gk : 0), bytes);                        \
            cp16(d + 10240, Alo + ro + (bytes ? gk : 0), bytes);                \
        }                                                                       \
    }
#define ISSUE_B4(c, stg)                                                        \
    {                                                                           \
        const int k0 = (c) << 5;                                                \
        const int gk = k0 + cch * 8;                                            \
        int kb = K - gk;                                                        \
        kb = kb < 0 ? 0 : (kb > 8 ? 8 : kb);                                    \
        kb *= 2;                                                                \
        _Pragma("unroll") for (int i = 0; i < NT / 32; i++) {                   \
            int n = crow + i * 32;                                              \
            int gn = n0 + n;                                                    \
            int bytes = (gn < Nreal) ? kb : 0;                                  \
            long ro = bytes ? (long)gn * ldb + gk : 0;                          \
            uint32_t d = sb0 + S4_B_BASE + (stg)*S4_STG +                       \
                         (uint32_t)(n * 80 + cch * 16);                         \
            cp16(d, Bhi + ro, bytes);                                           \
            cp16(d + 10240, Blo + ro, bytes);                                   \
        }                                                                       \
    }

    // prologue: group P0 = {A0, A1, B0}; group P1 = {A2, B1}
    ISSUE_A4(0, 0);
    if (1 < nChunks) ISSUE_A4(1, 1);
    ISSUE_B4(0, 0);
    cp_commit();
    if (2 < nChunks) ISSUE_A4(2, 2);
    if (1 < nChunks) ISSUE_B4(1, 1);
    cp_commit();

    for (int c = 0; c < nChunks; c++) {
        cp_wait<1>();
        __syncthreads();

        const uint32_t sa = sb0 + (uint32_t)((c % 3) * S4_STG);
        const uint32_t sbb = sb0 + (uint32_t)(S4_B_BASE + (c & 1) * S4_STG);
#pragma unroll
        for (int ks = 0; ks < 2; ks++) {
            uint32_t bh[8][2], bl[8][2];
#pragma unroll
            for (int p = 0; p < 4; p++) {
                uint32_t row = (uint32_t)(wn * 64 + p * 16 + ((lane >> 4) << 3) + (lane & 7));
                uint32_t off = row * 80 + (uint32_t)(ks * 32 + ((lane >> 3) & 1) * 16);
                uint32_t r4[4];
                ldm_x4(r4, sbb + off);
                bh[2 * p][0] = r4[0]; bh[2 * p][1] = r4[1];
                bh[2 * p + 1][0] = r4[2]; bh[2 * p + 1][1] = r4[3];
                ldm_x4(r4, sbb + 10240 + off);
                bl[2 * p][0] = r4[0]; bl[2 * p][1] = r4[1];
                bl[2 * p + 1][0] = r4[2]; bl[2 * p + 1][1] = r4[3];
            }
#pragma unroll
            for (int mi = 0; mi < MI; mi++) {
                uint32_t ah[4], al[4];
                uint32_t off = (uint32_t)((wm * (MI * 16) + mi * 16 + (lane & 15)) * 80 +
                                          ks * 32 + (lane >> 4) * 16);
                ldm_x4(ah, sa + off);
                ldm_x4(al, sa + 10240 + off);
#pragma unroll
                for (int ni = 0; ni < 8; ni++) {
                    mma16816(acc[mi][ni], ah, bh[ni]);
                    mma16816(acc[mi][ni], ah, bl[ni]);
                    mma16816(acc[mi][ni], al, bh[ni]);
                }
            }
        }
        __syncthreads();
        if (c + 3 < nChunks) ISSUE_A4(c + 3, (c + 3) % 3);
        if (c + 2 < nChunks) ISSUE_B4(c + 2, (c + 2) & 1);
        cp_commit();
    }
#undef ISSUE_A4
#undef ISSUE_B4

    const int trow = lane >> 2, tcol = (lane & 3) * 2;

    if constexpr (EPI == EPI_STORE) {
        __nv_bfloat16* Chi = g_act + offC + (long)b * sC;
        __nv_bfloat16* Clo = Chi + planeC;
#pragma unroll
        for (int mi = 0; mi < MI; mi++) {
            int r0 = m0 + wm * (MI * 16) + mi * 16 + trow;
#pragma unroll
            for (int ni = 0; ni < 8; ni++) {
                int c0 = n0 + wn * 64 + ni * 8 + tcol;
                if (c0 >= Nreal) continue;
                float v0 = acc[mi][ni][0], v1 = acc[mi][ni][1];
                float v2 = acc[mi][ni][2], v3 = acc[mi][ni][3];
                if (doRelu) {
                    v0 = fmaxf(v0, 0.f); v1 = fmaxf(v1, 0.f);
                    v2 = fmaxf(v2, 0.f); v3 = fmaxf(v3, 0.f);
                }
                __nv_bfloat162 h01, l01, h23, l23;
                split1(v0, h01.x, l01.x); split1(v1, h01.y, l01.y);
                split1(v2, h23.x, l23.x); split1(v3, h23.y, l23.y);
                long e0 = (long)r0 * ldc + c0, e1 = (long)(r0 + 8) * ldc + c0;
                *reinterpret_cast<__nv_bfloat162*>(Chi + e0) = h01;
                *reinterpret_cast<__nv_bfloat162*>(Clo + e0) = l01;
                *reinterpret_cast<__nv_bfloat162*>(Chi + e1) = h23;
                *reinterpret_cast<__nv_bfloat162*>(Clo + e1) = l23;
            }
        }
    } else {  // EPI_POOL: relu + masked row-sum -> g_scratch pool
        const int side = blockIdx.z;
        const float* mask = g_scratch + (side ? OFF_MASK2 : OFF_MASK1) + (long)blockIdx.y * Sn;
        float* smP = reinterpret_cast<float*>(smem);  // [WMC][NT]
        float p[8][2];
#pragma unroll
        for (int ni = 0; ni < 8; ni++) { p[ni][0] = 0.f; p[ni][1] = 0.f; }
#pragma unroll
        for (int mi = 0; mi < MI; mi++) {
            int r0 = wm * (MI * 16) + mi * 16 + trow;
            float m0v = mask[r0], m1v = mask[r0 + 8];
#pragma unroll
            for (int ni = 0; ni < 8; ni++) {
                p[ni][0] += fmaxf(acc[mi][ni][0], 0.f) * m0v + fmaxf(acc[mi][ni][2], 0.f) * m1v;
                p[ni][1] += fmaxf(acc[mi][ni][1], 0.f) * m0v + fmaxf(acc[mi][ni][3], 0.f) * m1v;
            }
        }
#pragma unroll
        for (int ni = 0; ni < 8; ni++) {
#pragma unroll
            for (int o = 4; o <= 16; o <<= 1) {
                p[ni][0] += __shfl_xor_sync(0xffffffffu, p[ni][0], o);
                p[ni][1] += __shfl_xor_sync(0xffffffffu, p[ni][1], o);
            }
        }
        __syncthreads();
        if (lane < 4) {
#pragma unroll
            for (int ni = 0; ni < 8; ni++) {
                smP[wm * NT + wn * 64 + ni * 8 + lane * 2] = p[ni][0];
                smP[wm * NT + wn * 64 + ni * 8 + lane * 2 + 1] = p[ni][1];
            }
        }
        __syncthreads();
        if (tid < NT) {
            int gcol = n0 + tid;
            if (gcol < Nreal) {
                float s = 0.f;
#pragma unroll
                for (int w = 0; w < WMC; w++) s += smP[w * NT + tid];
                g_scratch[OFF_POOL + (long)blockIdx.y * 800 + (long)side * 400 + gcol] = s;
            }
        }
    }
}

// ---------------------------------------------------------------------------
// All weights: transpose + split, one launch. W [K][N] f32 -> [N][Kp] hi/lo
// ---------------------------------------------------------------------------
__global__ void k_wsplit_all(const float* __restrict__ w_intra,
                             const float* __restrict__ w_proj1,
                             const float* __restrict__ w_proj2,
                             const float* __restrict__ w_att,
                             const float* __restrict__ w_cmp1,
                             const float* __restrict__ w_cmp2) {
    const float* W;
    int K, N, Kp;
    long off;
    switch (blockIdx.y) {
        case 0: W = w_intra; K = En;     N = En;     Kp = EP;     off = WT_INTRA; break;
        case 1: W = w_proj1; K = 2 * En; N = Pn;     Kp = 2 * En; off = WT_PROJ1; break;
        case 2: W = w_proj2; K = 2 * En; N = Pn;     Kp = 2 * En; off = WT_PROJ2; break;
        case 3: W = w_att;   K = Pn;     N = Pn;     Kp = Pn;     off = WT_ATT;   break;
        case 4: W = w_cmp1;  K = 2 * Pn; N = 2 * Pn; Kp = 2 * Pn; off = WT_CMP1;  break;
        default: W = w_cmp2; K = 2 * Pn; N = 2 * Pn; Kp = 2 * Pn; off = WT_CMP2;  break;
    }
    long total = (long)K * N;
    long plane = (long)N * Kp;
    for (long i = (long)blockIdx.x * blockDim.x + threadIdx.x; i < total;
         i += (long)gridDim.x * blockDim.x) {
        int n = (int)(i / K), k = (int)(i % K);
        float v = W[(long)k * N + n];
        __nv_bfloat16 h, l;
        split1(v, h, l);
        g_wt[off + (long)n * Kp + k] = h;
        g_wt[off + plane + (long)n * Kp + k] = l;
    }
}

// ---------------------------------------------------------------------------
// Non-GEMM kernels
// ---------------------------------------------------------------------------
__global__ void k_seqmask(const int* __restrict__ x1, const int* __restrict__ x2) {
    int b = blockIdx.x;
    const int* x = blockIdx.y ? x2 : x1;
    float* m = g_scratch + (blockIdx.y ? OFF_MASK2 : OFF_MASK1);
    int t = threadIdx.x;
    int nz = __syncthreads_count(x[b * Sn + t] != 0);
    m[b * Sn + t] = (t < nz) ? 1.0f : 0.0f;
}

// warp-per-token gather + L2 normalize: 256 threads = 8 tokens per block
__global__ void k_gather(const int* __restrict__ x1, const int* __restrict__ x2,
                         const float* __restrict__ emb) {
    int side = blockIdx.y;
    const int* x = side ? x2 : x1;
    int lane = threadIdx.x & 31;
    long bs = (long)blockIdx.x * 8 + (threadIdx.x >> 5);
    int row = x[bs];
    const float* e = emb + (long)row * En;
    float v[10];
    float ss = 0.f;
#pragma unroll
    for (int i = 0; i < 10; i++) {
        int idx = lane + i * 32;
        v[i] = (idx < En) ? e[idx] : 0.f;
        ss += v[i] * v[i];
    }
#pragma unroll
    for (int o = 16; o; o >>= 1) ss += __shfl_xor_sync(0xffffffffu, ss, o);
    float inv = 1.0f / sqrtf(fmaxf(ss, 1e-12f));
    __nv_bfloat16* hi = g_act + ACT_CAT + (long)side * BS * 600 + bs * 600;
    __nv_bfloat16* lo = hi + CAT_PL;
#pragma unroll
    for (int i = 0; i < 10; i++) {
        int idx = lane + i * 32;
        if (idx < En) {
            __nv_bfloat16 h, l;
            split1(v[i] * inv, h, l);
            hi[idx] = h;
            lo[idx] = l;
        }
    }
}

__global__ void k_final(const float* __restrict__ w_agg, float* __restrict__ out) {
    int b = blockIdx.x;
    int tid = threadIdx.x;
    int c = tid >> 5, lane = tid & 31;
    const float* p = g_scratch + OFF_POOL + (long)b * 800;
    float acc = 0.f;
    for (int n = lane; n < 800; n += 32) acc += p[n] * w_agg[n * Cn + c];
#pragma unroll
    for (int o = 16; o; o >>= 1) acc += __shfl_xor_sync(0xffffffffu, acc, o);
    if (lane == 0) out[b * Cn + c] = fmaxf(acc, 0.f);
}

// ---------------------------------------------------------------------------
// Orchestration
// ---------------------------------------------------------------------------
extern "C" void kernel_launch(void* const* d_in, const int* in_sizes, int n_in,
                              void* d_out, int out_size) {
    const int* x1 = (const int*)d_in[0];
    const int* x2 = (const int*)d_in[1];
    const float* emb = (const float*)d_in[2];
    const float* w_intra = (const float*)d_in[3];
    const float* bias_intra = (const float*)d_in[4];
    const float* w_proj1 = (const float*)d_in[5];
    const float* w_proj2 = (const float*)d_in[6];
    const float* w_att = (const float*)d_in[7];
    const float* w_cmp1 = (const float*)d_in[8];
    const float* w_cmp2 = (const float*)d_in[9];
    const float* w_agg = (const float*)d_in[10];
    float* out = (float*)d_out;

    cudaFuncSetAttribute(k_gemm8<EPI_STORE>, cudaFuncAttributeMaxDynamicSharedMemorySize, SMEM8_BYTES);
    cudaFuncSetAttribute(k_gemm8<EPI_ATT>, cudaFuncAttributeMaxDynamicSharedMemorySize, SMEM8_BYTES);
    cudaFuncSetAttribute(k_gemm8<EPI_SIM>, cudaFuncAttributeMaxDynamicSharedMemorySize, SMEM8_BYTES);
    cudaFuncSetAttribute((const void*)k_gemm4<EPI_STORE, 2>, cudaFuncAttributeMaxDynamicSharedMemorySize, SMEM4_BYTES);
    cudaFuncSetAttribute((const void*)k_gemm4<EPI_STORE, 1>, cudaFuncAttributeMaxDynamicSharedMemorySize, SMEM4_BYTES);
    cudaFuncSetAttribute((const void*)k_gemm4<EPI_POOL, 2>, cudaFuncAttributeMaxDynamicSharedMemorySize, SMEM4_BYTES);
    cudaFuncSetAttribute((const void*)k_gemm4<EPI_POOL, 1>, cudaFuncAttributeMaxDynamicSharedMemorySize, SMEM4_BYTES);

    k_seqmask<<<dim3(Bn, 2), Sn>>>(x1, x2);
    k_gather<<<dim3((unsigned)(BS / 8), 2), 256>>>(x1, x2, emb);
    k_wsplit_all<<<dim3(160, 6), 256>>>(w_intra, w_proj1, w_proj2, w_att, w_cmp1, w_cmp2);

    // f = relu(e @ w_intra): bulk 2 full tiles + 64-wide edge (N=300)
    k_gemm4<EPI_STORE, 2><<<dim3(2, 256, 2), 128, SMEM4_BYTES>>>(
        ACT_CAT, 600, BS * 600, CAT_PL,
        WT_INTRA, EP, 0, 300L * EP,
        ACT_F, EP, BS * EP, F_PL,
        0, En, En, 1);
    k_gemm4<EPI_STORE, 1><<<dim3(1, 256, 2), 128, SMEM4_BYTES>>>(
        ACT_CAT, 600, BS * 600, CAT_PL,
        WT_INTRA, EP, 0, 300L * EP,
        ACT_F, EP, BS * EP, F_PL,
        256, En, En, 1);

    // att = softmax_rows(f@f^T + dbias): symmetric (B == A tile)
    k_gemm8<EPI_ATT><<<dim3(1, 1, 2 * Bn), 256, SMEM8_BYTES>>>(
        ACT_F, EP, (long)Sn * EP, F_PL,
        1, ACT_F, EP, (long)Sn * EP, F_PL,
        ACT_ATT, Sn, (long)Sn * Sn, ATT_PL, 0, 0,
        NO_SPLIT, 0, 0, 0,
        Sn, En, 0, bias_intra, 1);

    // xp[g] = att[g] @ e[g]: B N-major -> cat cols 300:600
    k_gemm8<EPI_STORE><<<dim3(3, 1, 2 * Bn), 256, SMEM8_BYTES>>>(
        ACT_ATT, Sn, (long)Sn * Sn, ATT_PL,
        2, ACT_CAT, 600, (long)Sn * 600, CAT_PL,
        ACT_CAT + En, 600, (long)Sn * 600, CAT_PL, 0, 0,
        NO_SPLIT, 0, 0, 0,
        En, Sn, 0, nullptr, 0);

    // x_proj = relu(cat @ w_proj{1,2}): [2 x BS x 200], K=600
    k_gemm4<EPI_STORE, 2><<<dim3(2, 256, 2), 128, SMEM4_BYTES>>>(
        ACT_CAT, 600, BS * 600, CAT_PL,
        WT_PROJ1, 600, WT_PROJ2 - WT_PROJ1, 120000,
        ACT_CATP, 400, BS * 400, CATP_PL,
        0, Pn, 2 * En, 1);

    // fa = relu(x_proj @ w_att): [2 x BS x 200], K=200
    k_gemm4<EPI_STORE, 2><<<dim3(2, 256, 2), 128, SMEM4_BYTES>>>(
        ACT_CATP, 400, BS * 400, CATP_PL,
        WT_ATT, Pn, 0, 40000,
        ACT_FA, Pn, BS * Pn, FA_PL,
        0, Pn, Pn, 1);

    // sim: fused mask + row softmax (-> SIM) + col softmax^T (-> SMT)
    k_gemm8<EPI_SIM><<<dim3(1, 1, Bn), 256, SMEM8_BYTES>>>(
        ACT_FA, Pn, (long)Sn * Pn, FA_PL,
        1, ACT_FA + BS * Pn, Pn, (long)Sn * Pn, FA_PL,
        ACT_SIM, Sn, (long)Sn * Sn, SIM_PL,
        ACT_SMT, SMT_PL,
        NO_SPLIT, 0, 0, 0,
        Sn, Pn, 0, nullptr, 0);

    // beta (z<256) and alpha (z>=256) merged
    k_gemm8<EPI_STORE><<<dim3(2, 1, 2 * Bn), 256, SMEM8_BYTES>>>(
        ACT_SIM, Sn, (long)Sn * Sn, SIM_PL,
        2, ACT_CATP + BS * 400, 400, (long)Sn * 400, CATP_PL,
        ACT_CATP + Pn, 400, (long)Sn * 400, CATP_PL, 0, 0,
        Bn, ACT_SMT, ACT_CATP, ACT_CATP + BS * 400 + Pn,
        Pn, Sn, 0, nullptr, 0);

    // v = relu([xp|attend] @ w_cmp{1,2}) + pooling: bulk 3 tiles + 64-wide edge
    k_gemm4<EPI_POOL, 2><<<dim3(3, 256, 2), 128, SMEM4_BYTES>>>(
        ACT_CATP, 400, BS * 400, CATP_PL,
        WT_CMP1, 2 * Pn, WT_CMP2 - WT_CMP1, 160000,
        0, 0, 0, 0,
        0, 2 * Pn, 2 * Pn, 1);
    k_gemm4<EPI_POOL, 1><<<dim3(1, 256, 2), 128, SMEM4_BYTES>>>(
        ACT_CATP, 400, BS * 400, CATP_PL,
        WT_CMP1, 2 * Pn, WT_CMP2 - WT_CMP1, 160000,
        0, 0, 0, 0,
        384, 2 * Pn, 2 * Pn, 1);

    k_final<<<Bn, 96>>>(w_agg, out);
}